// round 1
// baseline (speedup 1.0000x reference)
#include <cuda_runtime.h>
#include <math.h>
#include <stdint.h>

// ---------------- problem constants ----------------
#define TTOK   2048      // B*S
#define BATCH  2
#define SEQ    1024
#define DIM    1024
#define HEADS  8
#define QK_HD  128
#define V_HD   128
#define NOPE   64
#define ROPE   64
#define KV_LORA 256
#define KVA_N  (KV_LORA + ROPE)   // 320
#define KVB_N  (HEADS * (NOPE + V_HD)) // 1536
#define N_EXP  32
#define N_GROUPS 8
#define TOPK   4
#define TOPK_G 4
#define INTER  512
#define NSLOT  (TTOK * TOPK)     // 8192
#define EPS    1e-6f
#define ATTN_SCALE 0.08838834764831843f  // 1/sqrt(128)

// ---------------- scratch (static device memory; no allocs) ----------------
__device__ float g_x1  [TTOK * DIM];
__device__ float g_q   [TTOK * DIM];
__device__ float g_kv  [TTOK * KVA_N];
__device__ float g_cn  [TTOK * KV_LORA];
__device__ float g_kvp [TTOK * KVB_N];
__device__ float g_attn[TTOK * DIM];
__device__ float g_x2  [TTOK * DIM];
__device__ float g_xf  [TTOK * DIM];
__device__ float g_g1  [TTOK * INTER];
__device__ float g_g3  [TTOK * INTER];
__device__ float g_hs  [TTOK * INTER];
__device__ float g_z   [TTOK * DIM];
__device__ float g_hbuf[NSLOT * INTER];
__device__ float g_ybuf[NSLOT * DIM];

__device__ int   g_counts [N_EXP];
__device__ int   g_offsets[N_EXP];
__device__ int   g_cursor [N_EXP];
__device__ int   g_expt_idx[NSLOT];
__device__ float g_expt_w [NSLOT];
__device__ int   g_perm_token[NSLOT];
__device__ float g_perm_w   [NSLOT];
__device__ int   g_slot_of  [NSLOT];

// ---------------- helpers ----------------
__device__ __forceinline__ float blockReduceSum256(float v) {
    __shared__ float red[8];
    int lane = threadIdx.x & 31, warp = threadIdx.x >> 5;
    #pragma unroll
    for (int o = 16; o > 0; o >>= 1) v += __shfl_xor_sync(0xffffffffu, v, o);
    if (lane == 0) red[warp] = v;
    __syncthreads();
    if (warp == 0) {
        v = (lane < 8) ? red[lane] : 0.f;
        #pragma unroll
        for (int o = 4; o > 0; o >>= 1) v += __shfl_xor_sync(0xffffffffu, v, o);
        if (lane == 0) red[0] = v;
    }
    __syncthreads();
    return red[0];
}

// ---------------- rmsnorm: one block (256 thr) per token ----------------
__global__ void rmsnorm_kernel(const float* __restrict__ x, const float* __restrict__ w,
                               float* __restrict__ out, int D, int in_stride) {
    int t = blockIdx.x;
    const float* row = x + (size_t)t * in_stride;
    float ss = 0.f;
    for (int d = threadIdx.x; d < D; d += 256) { float v = row[d]; ss += v * v; }
    ss = blockReduceSum256(ss);
    __shared__ float inv;
    if (threadIdx.x == 0) inv = rsqrtf(ss / (float)D + EPS);
    __syncthreads();
    for (int d = threadIdx.x; d < D; d += 256)
        out[(size_t)t * D + d] = row[d] * inv * w[d];
}

// ---------------- generic fp32 GEMM: C = A[MxK] @ B[KxN] (+resid) --------
// 64x64 tile, K-tile 16, 256 threads, 4x4 per thread.
__global__ void gemm_kernel(const float* __restrict__ A, const float* __restrict__ B,
                            float* __restrict__ C, const float* __restrict__ resid,
                            int M, int N, int K) {
    __shared__ float As[16][64];
    __shared__ float Bs[16][64];
    int bm = blockIdx.y * 64, bn = blockIdx.x * 64;
    int tid = threadIdx.x;
    int ty = tid >> 4, tx = tid & 15;
    float acc[4][4] = {};
    for (int kk = 0; kk < K; kk += 16) {
        #pragma unroll
        for (int i = 0; i < 4; i++) {
            int idx = tid + i * 256;
            int r = idx >> 4, c = idx & 15;
            As[c][r] = A[(size_t)(bm + r) * K + kk + c];
        }
        #pragma unroll
        for (int i = 0; i < 4; i++) {
            int idx = tid + i * 256;
            int r = idx >> 6, c = idx & 63;
            Bs[r][c] = B[(size_t)(kk + r) * N + bn + c];
        }
        __syncthreads();
        #pragma unroll
        for (int k = 0; k < 16; k++) {
            float a[4], b[4];
            #pragma unroll
            for (int i = 0; i < 4; i++) a[i] = As[k][ty * 4 + i];
            #pragma unroll
            for (int j = 0; j < 4; j++) b[j] = Bs[k][tx * 4 + j];
            #pragma unroll
            for (int i = 0; i < 4; i++)
                #pragma unroll
                for (int j = 0; j < 4; j++) acc[i][j] += a[i] * b[j];
        }
        __syncthreads();
    }
    #pragma unroll
    for (int i = 0; i < 4; i++)
        #pragma unroll
        for (int j = 0; j < 4; j++) {
            int r = bm + ty * 4 + i, c = bn + tx * 4 + j;
            float v = acc[i][j];
            if (resid) v += resid[(size_t)r * N + c];
            C[(size_t)r * N + c] = v;
        }
}

// ---------------- attention: 8-query tile per block, 128 threads ----------
__global__ void attn_kernel(const float* __restrict__ q, const float* __restrict__ kvp,
                            const float* __restrict__ kv, float* __restrict__ out) {
    int b = blockIdx.z, h = blockIdx.y;
    int i0 = blockIdx.x * 8;
    __shared__ float sc[8][SEQ];     // 32 KB
    __shared__ float qsm[8][128];
    __shared__ float lsum[8];
    int tid = threadIdx.x, warp = tid >> 5, lane = tid & 31;

    #pragma unroll
    for (int qi = 0; qi < 8; qi++)
        qsm[qi][tid] = q[(size_t)(b * SEQ + i0 + qi) * DIM + h * 128 + tid] * ATTN_SCALE;
    __syncthreads();

    int nkeys = i0 + 8;
    // scores: warp w handles keys j = w, w+4, ...
    for (int j = warp; j < nkeys; j += 4) {
        size_t tj = (size_t)(b * SEQ + j);
        float kd[4];
        #pragma unroll
        for (int u = 0; u < 4; u++) {
            int d = lane + 32 * u;
            kd[u] = (d < NOPE) ? kvp[tj * KVB_N + h * (NOPE + V_HD) + d]
                               : kv[tj * KVA_N + KV_LORA + (d - NOPE)];
        }
        #pragma unroll
        for (int qi = 0; qi < 8; qi++) {
            float s = 0.f;
            #pragma unroll
            for (int u = 0; u < 4; u++) s += qsm[qi][lane + 32 * u] * kd[u];
            #pragma unroll
            for (int o = 16; o > 0; o >>= 1) s += __shfl_xor_sync(0xffffffffu, s, o);
            if (lane == 0) sc[qi][j] = s;
        }
    }
    __syncthreads();
    // softmax per query: warp w handles queries w and w+4
    for (int qi = warp; qi < 8; qi += 4) {
        int lim = i0 + qi;
        float m = -1e30f;
        for (int j = lane; j <= lim; j += 32) m = fmaxf(m, sc[qi][j]);
        #pragma unroll
        for (int o = 16; o > 0; o >>= 1) m = fmaxf(m, __shfl_xor_sync(0xffffffffu, m, o));
        float l = 0.f;
        for (int j = lane; j <= lim; j += 32) { float p = expf(sc[qi][j] - m); sc[qi][j] = p; l += p; }
        for (int j = lim + 1 + lane; j < nkeys; j += 32) sc[qi][j] = 0.f;
        #pragma unroll
        for (int o = 16; o > 0; o >>= 1) l += __shfl_xor_sync(0xffffffffu, l, o);
        if (lane == 0) lsum[qi] = l;
    }
    __syncthreads();
    // PV: thread = one d column, coalesced V loads
    float acc[8] = {};
    for (int j = 0; j < nkeys; j++) {
        float v = kvp[(size_t)(b * SEQ + j) * KVB_N + h * (NOPE + V_HD) + NOPE + tid];
        #pragma unroll
        for (int qi = 0; qi < 8; qi++) acc[qi] += sc[qi][j] * v;
    }
    #pragma unroll
    for (int qi = 0; qi < 8; qi++)
        out[(size_t)(b * SEQ + i0 + qi) * DIM + h * 128 + tid] = acc[qi] / lsum[qi];
}

// ---------------- gate ----------------
__global__ void zero_counts_kernel() {
    if (threadIdx.x < N_EXP) g_counts[threadIdx.x] = 0;
}

__global__ void gate_kernel(const float* __restrict__ xf, const float* __restrict__ gw,
                            const float* __restrict__ gb) {
    int t = blockIdx.x;
    __shared__ float sscore[N_EXP];
    int tid = threadIdx.x, warp = tid >> 5, lane = tid & 31;
    for (int e = warp; e < N_EXP; e += 4) {
        float s = 0.f;
        for (int d = lane; d < DIM; d += 32) s += xf[(size_t)t * DIM + d] * gw[(size_t)e * DIM + d];
        #pragma unroll
        for (int o = 16; o > 0; o >>= 1) s += __shfl_xor_sync(0xffffffffu, s, o);
        if (lane == 0) sscore[e] = 1.f / (1.f + expf(-s));
    }
    __syncthreads();
    if (tid == 0) {
        float orig[N_EXP], s[N_EXP];
        for (int e = 0; e < N_EXP; e++) { orig[e] = sscore[e]; s[e] = orig[e] + gb[e]; }
        float gs[N_GROUPS];
        for (int g = 0; g < N_GROUPS; g++) {
            float m1 = -1e30f, m2 = -1e30f;
            for (int k = 0; k < 4; k++) {
                float v = s[g * 4 + k];
                if (v > m1) { m2 = m1; m1 = v; } else if (v > m2) m2 = v;
            }
            gs[g] = m1 + m2;
        }
        bool gsel[N_GROUPS] = {};
        for (int r = 0; r < TOPK_G; r++) {
            int best = -1; float bv = -1e30f;
            for (int g = 0; g < N_GROUPS; g++)
                if (!gsel[g] && gs[g] > bv) { bv = gs[g]; best = g; }
            gsel[best] = true;
        }
        for (int g = 0; g < N_GROUPS; g++)
            if (!gsel[g]) for (int k = 0; k < 4; k++) s[g * 4 + k] = -1e30f;
        int idx[TOPK]; bool used[N_EXP] = {};
        for (int r = 0; r < TOPK; r++) {
            int best = -1; float bv = -2e30f;
            for (int e = 0; e < N_EXP; e++)
                if (!used[e] && s[e] > bv) { bv = s[e]; best = e; }
            used[best] = true; idx[r] = best;
        }
        float wsum = 0.f;
        for (int r = 0; r < TOPK; r++) wsum += orig[idx[r]];
        float inv = 1.f / (wsum + 1e-20f);
        for (int r = 0; r < TOPK; r++) {
            g_expt_idx[t * TOPK + r] = idx[r];
            g_expt_w[t * TOPK + r] = orig[idx[r]] * inv;
            atomicAdd(&g_counts[idx[r]], 1);
        }
    }
}

__global__ void offsets_kernel() {
    if (threadIdx.x == 0) {
        int acc = 0;
        for (int e = 0; e < N_EXP; e++) {
            g_offsets[e] = acc;
            g_cursor[e] = acc;
            acc += g_counts[e];
        }
    }
}

__global__ void scatter_kernel() {
    int i = blockIdx.x * blockDim.x + threadIdx.x;
    if (i < NSLOT) {
        int e = g_expt_idx[i];
        int pos = atomicAdd(&g_cursor[e], 1);
        g_perm_token[pos] = i >> 2;
        g_perm_w[pos] = g_expt_w[i];
        g_slot_of[i] = pos;
    }
}

// ---------------- MoE grouped up-proj: h = silu(X@W1)*(X@W3) ------------
// grid: (mtiles=32, experts=32, ntiles=INTER/64). 256 thr, 32x64 tile, 2x4/thread x2.
__global__ void moe_up_kernel(const float* __restrict__ xf, const float* __restrict__ ew1,
                              const float* __restrict__ ew3) {
    int e = blockIdx.y;
    int cnt = g_counts[e];
    if (cnt == 0) return;
    int base = g_offsets[e];
    int bn = blockIdx.z * 64;
    const float* W1 = ew1 + (size_t)e * DIM * INTER;
    const float* W3 = ew3 + (size_t)e * DIM * INTER;
    __shared__ float As[16][32];
    __shared__ float B1s[16][64];
    __shared__ float B3s[16][64];
    int tid = threadIdx.x;
    int ty = tid >> 4, tx = tid & 15;

    for (int m0 = blockIdx.x * 32; m0 < cnt; m0 += 32 * gridDim.x) {
        float acc1[2][4] = {}, acc3[2][4] = {};
        for (int kk = 0; kk < DIM; kk += 16) {
            #pragma unroll
            for (int i = 0; i < 2; i++) {
                int idx = tid + i * 256;
                int r = idx >> 4, c = idx & 15;
                int tok = (m0 + r < cnt) ? g_perm_token[base + m0 + r] : 0;
                As[c][r] = xf[(size_t)tok * DIM + kk + c];
            }
            #pragma unroll
            for (int i = 0; i < 4; i++) {
                int idx = tid + i * 256;
                int r = idx >> 6, c = idx & 63;
                B1s[r][c] = W1[(size_t)(kk + r) * INTER + bn + c];
                B3s[r][c] = W3[(size_t)(kk + r) * INTER + bn + c];
            }
            __syncthreads();
            #pragma unroll
            for (int k = 0; k < 16; k++) {
                float a[2], b1[4], b3[4];
                a[0] = As[k][ty * 2]; a[1] = As[k][ty * 2 + 1];
                #pragma unroll
                for (int j = 0; j < 4; j++) { b1[j] = B1s[k][tx * 4 + j]; b3[j] = B3s[k][tx * 4 + j]; }
                #pragma unroll
                for (int i = 0; i < 2; i++)
                    #pragma unroll
                    for (int j = 0; j < 4; j++) {
                        acc1[i][j] += a[i] * b1[j];
                        acc3[i][j] += a[i] * b3[j];
                    }
            }
            __syncthreads();
        }
        #pragma unroll
        for (int i = 0; i < 2; i++) {
            int r = m0 + ty * 2 + i;
            if (r < cnt) {
                #pragma unroll
                for (int j = 0; j < 4; j++) {
                    float a = acc1[i][j];
                    float hval = (a / (1.f + expf(-a))) * acc3[i][j];
                    g_hbuf[(size_t)(base + r) * INTER + bn + tx * 4 + j] = hval;
                }
            }
        }
        __syncthreads();
    }
}

// ---------------- MoE grouped down-proj: ybuf[pos] = w * (h @ W2) --------
__global__ void moe_down_kernel(const float* __restrict__ ew2) {
    int e = blockIdx.y;
    int cnt = g_counts[e];
    if (cnt == 0) return;
    int base = g_offsets[e];
    int bn = blockIdx.z * 64;
    const float* W2 = ew2 + (size_t)e * INTER * DIM;
    __shared__ float As[16][32];
    __shared__ float Bs[16][64];
    int tid = threadIdx.x;
    int ty = tid >> 4, tx = tid & 15;

    for (int m0 = blockIdx.x * 32; m0 < cnt; m0 += 32 * gridDim.x) {
        float acc[2][4] = {};
        for (int kk = 0; kk < INTER; kk += 16) {
            #pragma unroll
            for (int i = 0; i < 2; i++) {
                int idx = tid + i * 256;
                int r = idx >> 4, c = idx & 15;
                As[c][r] = (m0 + r < cnt) ? g_hbuf[(size_t)(base + m0 + r) * INTER + kk + c] : 0.f;
            }
            #pragma unroll
            for (int i = 0; i < 4; i++) {
                int idx = tid + i * 256;
                int r = idx >> 6, c = idx & 63;
                Bs[r][c] = W2[(size_t)(kk + r) * DIM + bn + c];
            }
            __syncthreads();
            #pragma unroll
            for (int k = 0; k < 16; k++) {
                float a[2], b[4];
                a[0] = As[k][ty * 2]; a[1] = As[k][ty * 2 + 1];
                #pragma unroll
                for (int j = 0; j < 4; j++) b[j] = Bs[k][tx * 4 + j];
                #pragma unroll
                for (int i = 0; i < 2; i++)
                    #pragma unroll
                    for (int j = 0; j < 4; j++) acc[i][j] += a[i] * b[j];
            }
            __syncthreads();
        }
        #pragma unroll
        for (int i = 0; i < 2; i++) {
            int r = m0 + ty * 2 + i;
            if (r < cnt) {
                float w = g_perm_w[base + r];
                #pragma unroll
                for (int j = 0; j < 4; j++)
                    g_ybuf[(size_t)(base + r) * DIM + bn + tx * 4 + j] = w * acc[i][j];
            }
        }
        __syncthreads();
    }
}

// ---------------- shared-expert activation: hs = silu(g1)*g3 -------------
__global__ void silu_mul_kernel(const float* __restrict__ a, const float* __restrict__ b,
                                float* __restrict__ out, int n) {
    int i = blockIdx.x * blockDim.x + threadIdx.x;
    if (i < n) {
        float av = a[i];
        out[i] = (av / (1.f + expf(-av))) * b[i];
    }
}

// ---------------- final: out = x2 + z + sum_slots ybuf --------------------
__global__ void final_kernel(float* __restrict__ out) {
    int t = blockIdx.x;
    int s0 = g_slot_of[t * 4 + 0], s1 = g_slot_of[t * 4 + 1];
    int s2 = g_slot_of[t * 4 + 2], s3 = g_slot_of[t * 4 + 3];
    for (int d = threadIdx.x; d < DIM; d += 256) {
        float v = g_x2[(size_t)t * DIM + d] + g_z[(size_t)t * DIM + d];
        v += g_ybuf[(size_t)s0 * DIM + d];
        v += g_ybuf[(size_t)s1 * DIM + d];
        v += g_ybuf[(size_t)s2 * DIM + d];
        v += g_ybuf[(size_t)s3 * DIM + d];
        out[(size_t)t * DIM + d] = v;
    }
}

// ---------------- launcher ----------------
extern "C" void kernel_launch(void* const* d_in, const int* in_sizes, int n_in,
                              void* d_out, int out_size) {
    const float* x       = (const float*)d_in[0];
    const float* norm_a  = (const float*)d_in[1];
    const float* wq      = (const float*)d_in[2];
    const float* wkv_a   = (const float*)d_in[3];
    const float* kvnw    = (const float*)d_in[4];
    const float* wkv_b   = (const float*)d_in[5];
    const float* wo      = (const float*)d_in[6];
    const float* norm_m  = (const float*)d_in[7];
    const float* gate_w  = (const float*)d_in[8];
    const float* gate_b  = (const float*)d_in[9];
    const float* ew1     = (const float*)d_in[10];
    const float* ew2     = (const float*)d_in[11];
    const float* ew3     = (const float*)d_in[12];
    const float* sw1     = (const float*)d_in[13];
    const float* sw2     = (const float*)d_in[14];
    const float* sw3     = (const float*)d_in[15];
    float* out = (float*)d_out;

    float *x1, *q, *kv, *cn, *kvp, *attn, *x2, *xf, *g1, *g3, *hs, *z;
    cudaGetSymbolAddress((void**)&x1,  g_x1);
    cudaGetSymbolAddress((void**)&q,   g_q);
    cudaGetSymbolAddress((void**)&kv,  g_kv);
    cudaGetSymbolAddress((void**)&cn,  g_cn);
    cudaGetSymbolAddress((void**)&kvp, g_kvp);
    cudaGetSymbolAddress((void**)&attn,g_attn);
    cudaGetSymbolAddress((void**)&x2,  g_x2);
    cudaGetSymbolAddress((void**)&xf,  g_xf);
    cudaGetSymbolAddress((void**)&g1,  g_g1);
    cudaGetSymbolAddress((void**)&g3,  g_g3);
    cudaGetSymbolAddress((void**)&hs,  g_hs);
    cudaGetSymbolAddress((void**)&z,   g_z);

    // 1) attention input norm
    rmsnorm_kernel<<<TTOK, 256>>>(x, norm_a, x1, DIM, DIM);
    // 2) q = x1 @ wq   (2048x1024x1024)
    gemm_kernel<<<dim3(DIM/64, TTOK/64), 256>>>(x1, wq, q, nullptr, TTOK, DIM, DIM);
    // 3) kv = x1 @ wkv_a  (2048x1024x320)
    gemm_kernel<<<dim3(KVA_N/64, TTOK/64), 256>>>(x1, wkv_a, kv, nullptr, TTOK, KVA_N, DIM);
    // 4) cn = rmsnorm(kv[:, :256])
    rmsnorm_kernel<<<TTOK, 256>>>(kv, kvnw, cn, KV_LORA, KVA_N);
    // 5) kvp = cn @ wkv_b  (2048x256x1536)
    gemm_kernel<<<dim3(KVB_N/64, TTOK/64), 256>>>(cn, wkv_b, kvp, nullptr, TTOK, KVB_N, KV_LORA);
    // 6) attention
    attn_kernel<<<dim3(SEQ/8, HEADS, BATCH), 128>>>(q, kvp, kv, attn);
    // 7) x2 = x + attn @ wo
    gemm_kernel<<<dim3(DIM/64, TTOK/64), 256>>>(attn, wo, x2, x, TTOK, DIM, DIM);
    // 8) moe input norm
    rmsnorm_kernel<<<TTOK, 256>>>(x2, norm_m, xf, DIM, DIM);
    // 9) gate + routing
    zero_counts_kernel<<<1, 32>>>();
    gate_kernel<<<TTOK, 128>>>(xf, gate_w, gate_b);
    offsets_kernel<<<1, 32>>>();
    scatter_kernel<<<NSLOT/256, 256>>>();
    // 10) routed experts (grouped GEMMs)
    moe_up_kernel<<<dim3(32, N_EXP, INTER/64), 256>>>(xf, ew1, ew3);
    moe_down_kernel<<<dim3(32, N_EXP, DIM/64), 256>>>(ew2);
    // 11) shared expert
    gemm_kernel<<<dim3(INTER/64, TTOK/64), 256>>>(xf, sw1, g1, nullptr, TTOK, INTER, DIM);
    gemm_kernel<<<dim3(INTER/64, TTOK/64), 256>>>(xf, sw3, g3, nullptr, TTOK, INTER, DIM);
    silu_mul_kernel<<<(TTOK*INTER + 255)/256, 256>>>(g1, g3, hs, TTOK*INTER);
    gemm_kernel<<<dim3(DIM/64, TTOK/64), 256>>>(hs, sw2, z, nullptr, TTOK, DIM, INTER);
    // 12) final combine
    final_kernel<<<TTOK, 256>>>(out);
}

// round 2
// speedup vs baseline: 2.0732x; 2.0732x over previous
#include <cuda_runtime.h>
#include <math.h>
#include <stdint.h>

// ---------------- problem constants ----------------
#define TTOK   2048      // B*S
#define BATCH  2
#define SEQ    1024
#define DIM    1024
#define HEADS  8
#define QK_HD  128
#define V_HD   128
#define NOPE   64
#define ROPE   64
#define KV_LORA 256
#define KVA_N  (KV_LORA + ROPE)   // 320
#define KVB_N  (HEADS * (NOPE + V_HD)) // 1536
#define N_EXP  32
#define N_GROUPS 8
#define TOPK   4
#define TOPK_G 4
#define INTER  512
#define NSLOT  (TTOK * TOPK)     // 8192
#define EPS    1e-6f
#define ATTN_SCALE 0.08838834764831843f  // 1/sqrt(128)

// ---------------- scratch (static device memory; no allocs) ----------------
__device__ float g_x1  [TTOK * DIM];
__device__ float g_q   [TTOK * DIM];
__device__ float g_kv  [TTOK * KVA_N];
__device__ float g_cn  [TTOK * KV_LORA];
__device__ float g_kvp [TTOK * KVB_N];
__device__ float g_attn[TTOK * DIM];
__device__ float g_x2  [TTOK * DIM];
__device__ float g_xf  [TTOK * DIM];
__device__ float g_g1  [TTOK * INTER];
__device__ float g_g3  [TTOK * INTER];
__device__ float g_hs  [TTOK * INTER];
__device__ float g_z   [TTOK * DIM];
__device__ float g_u1  [NSLOT * INTER];
__device__ float g_u3  [NSLOT * INTER];
__device__ float g_hbuf[NSLOT * INTER];
__device__ float g_ybuf[NSLOT * DIM];

__device__ int   g_counts [N_EXP];
__device__ int   g_offsets[N_EXP];
__device__ int   g_cursor [N_EXP];
__device__ int   g_expt_idx[NSLOT];
__device__ float g_expt_w [NSLOT];
__device__ int   g_perm_token[NSLOT];
__device__ float g_perm_w   [NSLOT];
__device__ int   g_slot_of  [NSLOT];

// ---------------- helpers ----------------
__device__ __forceinline__ float blockReduceSum256(float v) {
    __shared__ float red[8];
    int lane = threadIdx.x & 31, warp = threadIdx.x >> 5;
    #pragma unroll
    for (int o = 16; o > 0; o >>= 1) v += __shfl_xor_sync(0xffffffffu, v, o);
    if (lane == 0) red[warp] = v;
    __syncthreads();
    if (warp == 0) {
        v = (lane < 8) ? red[lane] : 0.f;
        #pragma unroll
        for (int o = 4; o > 0; o >>= 1) v += __shfl_xor_sync(0xffffffffu, v, o);
        if (lane == 0) red[0] = v;
    }
    __syncthreads();
    return red[0];
}

__device__ __forceinline__ float f2tf32(float x) {
    uint32_t r;
    asm("cvt.rna.tf32.f32 %0, %1;" : "=r"(r) : "f"(x));
    return __uint_as_float(r);
}

__device__ __forceinline__ void mma_tf32(float* c, const uint32_t* a, const uint32_t* b) {
    asm volatile(
        "mma.sync.aligned.m16n8k8.row.col.f32.tf32.tf32.f32 "
        "{%0,%1,%2,%3}, {%4,%5,%6,%7}, {%8,%9}, {%0,%1,%2,%3};\n"
        : "+f"(c[0]), "+f"(c[1]), "+f"(c[2]), "+f"(c[3])
        : "r"(a[0]), "r"(a[1]), "r"(a[2]), "r"(a[3]), "r"(b[0]), "r"(b[1]));
}

// ---------------- rmsnorm ----------------
__global__ void rmsnorm_kernel(const float* __restrict__ x, const float* __restrict__ w,
                               float* __restrict__ out, int D, int in_stride) {
    int t = blockIdx.x;
    const float* row = x + (size_t)t * in_stride;
    float ss = 0.f;
    for (int d = threadIdx.x; d < D; d += 256) { float v = row[d]; ss += v * v; }
    ss = blockReduceSum256(ss);
    __shared__ float inv;
    if (threadIdx.x == 0) inv = rsqrtf(ss / (float)D + EPS);
    __syncthreads();
    for (int d = threadIdx.x; d < D; d += 256)
        out[(size_t)t * D + d] = row[d] * inv * w[d];
}

// ---------------- tf32 tensor-core GEMM --------------------------------
// MODE 0: C[M,N] = A[M,K] @ B[K,N] (+resid)
// MODE 1: per-expert (blockIdx.z), A rows gathered via g_perm_token
// MODE 2: per-expert, A rows = base+..., output scaled by g_perm_w
// 128x128x32 tile, 256 threads, 8 warps (2M x 4N), warp tile 64x32.
template<int MODE>
__global__ void __launch_bounds__(256, 1)
gemm_tf32_kernel(const float* __restrict__ A, const float* __restrict__ Bmat,
                 float* __restrict__ C, const float* __restrict__ resid,
                 int M, int N, int K) {
    __shared__ float As[128][36];   // [m][k], pad 4 -> bank-conflict-free frag loads
    __shared__ float Bs[32][132];   // [k][n], pad 4

    int tid = threadIdx.x;
    int warp = tid >> 5, lane = tid & 31;
    int g = lane >> 2, tig = lane & 3;
    int wm = warp >> 2, wn = warp & 3;       // 2 x 4 warp grid
    int m0w = wm * 64, n0w = wn * 32;

    int bn = blockIdx.x * 128;
    int bm, cnt = 0, base = 0;
    const float* Bp = Bmat;
    if (MODE == 0) {
        bm = blockIdx.y * 128;
    } else {
        int e = blockIdx.z;
        cnt = g_counts[e];
        base = g_offsets[e];
        bm = blockIdx.y * 128;
        if (bm >= cnt) return;
        Bp = Bmat + (size_t)e * K * N;
    }

    float cacc[4][4][4];
    #pragma unroll
    for (int a = 0; a < 4; a++)
        #pragma unroll
        for (int b = 0; b < 4; b++)
            #pragma unroll
            for (int c = 0; c < 4; c++) cacc[a][b][c] = 0.f;

    float4 ra[4], rb[4];

    // ---- stage loader (kk tile) ----
    auto stage = [&](int kk) {
        #pragma unroll
        for (int i = 0; i < 4; i++) {
            int fidx = tid + i * 256;
            int r = fidx >> 3, c4 = fidx & 7;
            float4 v = make_float4(0.f, 0.f, 0.f, 0.f);
            if (MODE == 0) {
                int row = bm + r;
                if (row < M) v = *(const float4*)&A[(size_t)row * K + kk + c4 * 4];
            } else if (MODE == 1) {
                if (bm + r < cnt) {
                    int tok = g_perm_token[base + bm + r];
                    v = *(const float4*)&A[(size_t)tok * K + kk + c4 * 4];
                }
            } else {
                if (bm + r < cnt)
                    v = *(const float4*)&A[(size_t)(base + bm + r) * K + kk + c4 * 4];
            }
            ra[i] = v;
        }
        #pragma unroll
        for (int i = 0; i < 4; i++) {
            int fidx = tid + i * 256;
            int r = fidx >> 5, c4 = fidx & 31;
            int col = bn + c4 * 4;
            float4 v = make_float4(0.f, 0.f, 0.f, 0.f);
            if (col < N) v = *(const float4*)&Bp[(size_t)(kk + r) * N + col];
            rb[i] = v;
        }
    };

    stage(0);

    for (int kk = 0; kk < K; kk += 32) {
        // sts with tf32 RNA conversion
        #pragma unroll
        for (int i = 0; i < 4; i++) {
            int fidx = tid + i * 256;
            int r = fidx >> 3, c4 = fidx & 7;
            As[r][c4 * 4 + 0] = f2tf32(ra[i].x);
            As[r][c4 * 4 + 1] = f2tf32(ra[i].y);
            As[r][c4 * 4 + 2] = f2tf32(ra[i].z);
            As[r][c4 * 4 + 3] = f2tf32(ra[i].w);
        }
        #pragma unroll
        for (int i = 0; i < 4; i++) {
            int fidx = tid + i * 256;
            int r = fidx >> 5, c4 = fidx & 31;
            Bs[r][c4 * 4 + 0] = f2tf32(rb[i].x);
            Bs[r][c4 * 4 + 1] = f2tf32(rb[i].y);
            Bs[r][c4 * 4 + 2] = f2tf32(rb[i].z);
            Bs[r][c4 * 4 + 3] = f2tf32(rb[i].w);
        }
        __syncthreads();

        if (kk + 32 < K) stage(kk + 32);   // overlap next-tile ldg with compute

        #pragma unroll
        for (int ks = 0; ks < 4; ks++) {
            int k0 = ks * 8;
            uint32_t afr[4][4], bfr[4][2];
            #pragma unroll
            for (int mt = 0; mt < 4; mt++) {
                int r0 = m0w + mt * 16 + g;
                afr[mt][0] = __float_as_uint(As[r0][k0 + tig]);
                afr[mt][1] = __float_as_uint(As[r0 + 8][k0 + tig]);
                afr[mt][2] = __float_as_uint(As[r0][k0 + tig + 4]);
                afr[mt][3] = __float_as_uint(As[r0 + 8][k0 + tig + 4]);
            }
            #pragma unroll
            for (int nt = 0; nt < 4; nt++) {
                int c0 = n0w + nt * 8 + g;
                bfr[nt][0] = __float_as_uint(Bs[k0 + tig][c0]);
                bfr[nt][1] = __float_as_uint(Bs[k0 + tig + 4][c0]);
            }
            #pragma unroll
            for (int mt = 0; mt < 4; mt++)
                #pragma unroll
                for (int nt = 0; nt < 4; nt++)
                    mma_tf32(cacc[mt][nt], afr[mt], bfr[nt]);
        }
        __syncthreads();
    }

    // ---- epilogue ----
    #pragma unroll
    for (int mt = 0; mt < 4; mt++) {
        int lr0 = bm + m0w + mt * 16 + g;
        #pragma unroll
        for (int half = 0; half < 2; half++) {
            int lr = lr0 + half * 8;
            bool rowok = (MODE == 0) ? (lr < M) : (lr < cnt);
            if (!rowok) continue;
            size_t orow = (MODE == 0) ? (size_t)lr : (size_t)(base + lr);
            float scale = 1.f;
            if (MODE == 2) scale = g_perm_w[base + lr];
            #pragma unroll
            for (int nt = 0; nt < 4; nt++) {
                int col = bn + n0w + nt * 8 + 2 * tig;
                float v0 = cacc[mt][nt][half * 2 + 0];
                float v1 = cacc[mt][nt][half * 2 + 1];
                if (MODE == 2) { v0 *= scale; v1 *= scale; }
                if (MODE == 0 && resid) {
                    if (col < N) v0 += resid[orow * N + col];
                    if (col + 1 < N) v1 += resid[orow * N + col + 1];
                }
                if (col < N) C[orow * N + col] = v0;
                if (col + 1 < N) C[orow * N + col + 1] = v1;
            }
        }
    }
}

// ---------------- attention: 8-query tile per block, 128 threads ----------
__global__ void attn_kernel(const float* __restrict__ q, const float* __restrict__ kvp,
                            const float* __restrict__ kv, float* __restrict__ out) {
    int b = blockIdx.z, h = blockIdx.y;
    int i0 = blockIdx.x * 8;
    __shared__ float sc[8][SEQ];
    __shared__ float qsm[8][128];
    __shared__ float lsum[8];
    int tid = threadIdx.x, warp = tid >> 5, lane = tid & 31;

    #pragma unroll
    for (int qi = 0; qi < 8; qi++)
        qsm[qi][tid] = q[(size_t)(b * SEQ + i0 + qi) * DIM + h * 128 + tid] * ATTN_SCALE;
    __syncthreads();

    int nkeys = i0 + 8;
    for (int j = warp; j < nkeys; j += 4) {
        size_t tj = (size_t)(b * SEQ + j);
        float kd[4];
        #pragma unroll
        for (int u = 0; u < 4; u++) {
            int d = lane + 32 * u;
            kd[u] = (d < NOPE) ? kvp[tj * KVB_N + h * (NOPE + V_HD) + d]
                               : kv[tj * KVA_N + KV_LORA + (d - NOPE)];
        }
        #pragma unroll
        for (int qi = 0; qi < 8; qi++) {
            float s = 0.f;
            #pragma unroll
            for (int u = 0; u < 4; u++) s += qsm[qi][lane + 32 * u] * kd[u];
            #pragma unroll
            for (int o = 16; o > 0; o >>= 1) s += __shfl_xor_sync(0xffffffffu, s, o);
            if (lane == 0) sc[qi][j] = s;
        }
    }
    __syncthreads();
    for (int qi = warp; qi < 8; qi += 4) {
        int lim = i0 + qi;
        float m = -1e30f;
        for (int j = lane; j <= lim; j += 32) m = fmaxf(m, sc[qi][j]);
        #pragma unroll
        for (int o = 16; o > 0; o >>= 1) m = fmaxf(m, __shfl_xor_sync(0xffffffffu, m, o));
        float l = 0.f;
        for (int j = lane; j <= lim; j += 32) { float p = expf(sc[qi][j] - m); sc[qi][j] = p; l += p; }
        for (int j = lim + 1 + lane; j < nkeys; j += 32) sc[qi][j] = 0.f;
        #pragma unroll
        for (int o = 16; o > 0; o >>= 1) l += __shfl_xor_sync(0xffffffffu, l, o);
        if (lane == 0) lsum[qi] = l;
    }
    __syncthreads();
    float acc[8] = {};
    for (int j = 0; j < nkeys; j++) {
        float v = kvp[(size_t)(b * SEQ + j) * KVB_N + h * (NOPE + V_HD) + NOPE + tid];
        #pragma unroll
        for (int qi = 0; qi < 8; qi++) acc[qi] += sc[qi][j] * v;
    }
    #pragma unroll
    for (int qi = 0; qi < 8; qi++)
        out[(size_t)(b * SEQ + i0 + qi) * DIM + h * 128 + tid] = acc[qi] / lsum[qi];
}

// ---------------- gate ----------------
__global__ void zero_counts_kernel() {
    if (threadIdx.x < N_EXP) g_counts[threadIdx.x] = 0;
}

__global__ void gate_kernel(const float* __restrict__ xf, const float* __restrict__ gw,
                            const float* __restrict__ gb) {
    int t = blockIdx.x;
    __shared__ float sscore[N_EXP];
    int tid = threadIdx.x, warp = tid >> 5, lane = tid & 31;
    for (int e = warp; e < N_EXP; e += 4) {
        float s = 0.f;
        for (int d = lane; d < DIM; d += 32) s += xf[(size_t)t * DIM + d] * gw[(size_t)e * DIM + d];
        #pragma unroll
        for (int o = 16; o > 0; o >>= 1) s += __shfl_xor_sync(0xffffffffu, s, o);
        if (lane == 0) sscore[e] = 1.f / (1.f + expf(-s));
    }
    __syncthreads();
    if (tid == 0) {
        float orig[N_EXP], s[N_EXP];
        for (int e = 0; e < N_EXP; e++) { orig[e] = sscore[e]; s[e] = orig[e] + gb[e]; }
        float gs[N_GROUPS];
        for (int gg = 0; gg < N_GROUPS; gg++) {
            float m1 = -1e30f, m2 = -1e30f;
            for (int k = 0; k < 4; k++) {
                float v = s[gg * 4 + k];
                if (v > m1) { m2 = m1; m1 = v; } else if (v > m2) m2 = v;
            }
            gs[gg] = m1 + m2;
        }
        bool gsel[N_GROUPS] = {};
        for (int r = 0; r < TOPK_G; r++) {
            int best = -1; float bv = -1e30f;
            for (int gg = 0; gg < N_GROUPS; gg++)
                if (!gsel[gg] && gs[gg] > bv) { bv = gs[gg]; best = gg; }
            gsel[best] = true;
        }
        for (int gg = 0; gg < N_GROUPS; gg++)
            if (!gsel[gg]) for (int k = 0; k < 4; k++) s[gg * 4 + k] = -1e30f;
        int idx[TOPK]; bool used[N_EXP] = {};
        for (int r = 0; r < TOPK; r++) {
            int best = -1; float bv = -2e30f;
            for (int e = 0; e < N_EXP; e++)
                if (!used[e] && s[e] > bv) { bv = s[e]; best = e; }
            used[best] = true; idx[r] = best;
        }
        float wsum = 0.f;
        for (int r = 0; r < TOPK; r++) wsum += orig[idx[r]];
        float inv = 1.f / (wsum + 1e-20f);
        for (int r = 0; r < TOPK; r++) {
            g_expt_idx[t * TOPK + r] = idx[r];
            g_expt_w[t * TOPK + r] = orig[idx[r]] * inv;
            atomicAdd(&g_counts[idx[r]], 1);
        }
    }
}

__global__ void offsets_kernel() {
    if (threadIdx.x == 0) {
        int acc = 0;
        for (int e = 0; e < N_EXP; e++) {
            g_offsets[e] = acc;
            g_cursor[e] = acc;
            acc += g_counts[e];
        }
    }
}

__global__ void scatter_kernel() {
    int i = blockIdx.x * blockDim.x + threadIdx.x;
    if (i < NSLOT) {
        int e = g_expt_idx[i];
        int pos = atomicAdd(&g_cursor[e], 1);
        g_perm_token[pos] = i >> 2;
        g_perm_w[pos] = g_expt_w[i];
        g_slot_of[i] = pos;
    }
}

// ---------------- elementwise: silu(a)*b --------------------------------
__global__ void silu_mul_kernel(const float* __restrict__ a, const float* __restrict__ b,
                                float* __restrict__ out, int n) {
    int i = blockIdx.x * blockDim.x + threadIdx.x;
    if (i < n) {
        float av = a[i];
        out[i] = (av / (1.f + expf(-av))) * b[i];
    }
}

// ---------------- final: out = x2 + z + sum_slots ybuf --------------------
__global__ void final_kernel(float* __restrict__ out) {
    int t = blockIdx.x;
    int s0 = g_slot_of[t * 4 + 0], s1 = g_slot_of[t * 4 + 1];
    int s2 = g_slot_of[t * 4 + 2], s3 = g_slot_of[t * 4 + 3];
    for (int d = threadIdx.x; d < DIM; d += 256) {
        float v = g_x2[(size_t)t * DIM + d] + g_z[(size_t)t * DIM + d];
        v += g_ybuf[(size_t)s0 * DIM + d];
        v += g_ybuf[(size_t)s1 * DIM + d];
        v += g_ybuf[(size_t)s2 * DIM + d];
        v += g_ybuf[(size_t)s3 * DIM + d];
        out[(size_t)t * DIM + d] = v;
    }
}

// ---------------- launcher ----------------
extern "C" void kernel_launch(void* const* d_in, const int* in_sizes, int n_in,
                              void* d_out, int out_size) {
    const float* x       = (const float*)d_in[0];
    const float* norm_a  = (const float*)d_in[1];
    const float* wq      = (const float*)d_in[2];
    const float* wkv_a   = (const float*)d_in[3];
    const float* kvnw    = (const float*)d_in[4];
    const float* wkv_b   = (const float*)d_in[5];
    const float* wo      = (const float*)d_in[6];
    const float* norm_m  = (const float*)d_in[7];
    const float* gate_w  = (const float*)d_in[8];
    const float* gate_b  = (const float*)d_in[9];
    const float* ew1     = (const float*)d_in[10];
    const float* ew2     = (const float*)d_in[11];
    const float* ew3     = (const float*)d_in[12];
    const float* sw1     = (const float*)d_in[13];
    const float* sw2     = (const float*)d_in[14];
    const float* sw3     = (const float*)d_in[15];
    float* out = (float*)d_out;

    float *x1, *q, *kv, *cn, *kvp, *attn, *x2, *xf, *g1, *g3, *hs, *z, *u1, *u3, *hbuf, *ybuf;
    cudaGetSymbolAddress((void**)&x1,  g_x1);
    cudaGetSymbolAddress((void**)&q,   g_q);
    cudaGetSymbolAddress((void**)&kv,  g_kv);
    cudaGetSymbolAddress((void**)&cn,  g_cn);
    cudaGetSymbolAddress((void**)&kvp, g_kvp);
    cudaGetSymbolAddress((void**)&attn,g_attn);
    cudaGetSymbolAddress((void**)&x2,  g_x2);
    cudaGetSymbolAddress((void**)&xf,  g_xf);
    cudaGetSymbolAddress((void**)&g1,  g_g1);
    cudaGetSymbolAddress((void**)&g3,  g_g3);
    cudaGetSymbolAddress((void**)&hs,  g_hs);
    cudaGetSymbolAddress((void**)&z,   g_z);
    cudaGetSymbolAddress((void**)&u1,  g_u1);
    cudaGetSymbolAddress((void**)&u3,  g_u3);
    cudaGetSymbolAddress((void**)&hbuf,g_hbuf);
    cudaGetSymbolAddress((void**)&ybuf,g_ybuf);

    // 1) attention input norm
    rmsnorm_kernel<<<TTOK, 256>>>(x, norm_a, x1, DIM, DIM);
    // 2) q = x1 @ wq
    gemm_tf32_kernel<0><<<dim3(DIM/128, TTOK/128), 256>>>(x1, wq, q, nullptr, TTOK, DIM, DIM);
    // 3) kv = x1 @ wkv_a (N=320 -> 3 n-tiles)
    gemm_tf32_kernel<0><<<dim3(3, TTOK/128), 256>>>(x1, wkv_a, kv, nullptr, TTOK, KVA_N, DIM);
    // 4) cn = rmsnorm(kv[:, :256])
    rmsnorm_kernel<<<TTOK, 256>>>(kv, kvnw, cn, KV_LORA, KVA_N);
    // 5) kvp = cn @ wkv_b
    gemm_tf32_kernel<0><<<dim3(KVB_N/128, TTOK/128), 256>>>(cn, wkv_b, kvp, nullptr, TTOK, KVB_N, KV_LORA);
    // 6) attention
    attn_kernel<<<dim3(SEQ/8, HEADS, BATCH), 128>>>(q, kvp, kv, attn);
    // 7) x2 = x + attn @ wo
    gemm_tf32_kernel<0><<<dim3(DIM/128, TTOK/128), 256>>>(attn, wo, x2, x, TTOK, DIM, DIM);
    // 8) moe input norm
    rmsnorm_kernel<<<TTOK, 256>>>(x2, norm_m, xf, DIM, DIM);
    // 9) gate + routing
    zero_counts_kernel<<<1, 32>>>();
    gate_kernel<<<TTOK, 128>>>(xf, gate_w, gate_b);
    offsets_kernel<<<1, 32>>>();
    scatter_kernel<<<NSLOT/256, 256>>>();
    // 10) routed experts (grouped tf32 GEMMs)
    gemm_tf32_kernel<1><<<dim3(INTER/128, TTOK/128, N_EXP), 256>>>(xf, ew1, u1, nullptr, 0, INTER, DIM);
    gemm_tf32_kernel<1><<<dim3(INTER/128, TTOK/128, N_EXP), 256>>>(xf, ew3, u3, nullptr, 0, INTER, DIM);
    silu_mul_kernel<<<(NSLOT*INTER + 255)/256, 256>>>(u1, u3, hbuf, NSLOT*INTER);
    gemm_tf32_kernel<2><<<dim3(DIM/128, TTOK/128, N_EXP), 256>>>(hbuf, ew2, ybuf, nullptr, 0, DIM, INTER);
    // 11) shared expert
    gemm_tf32_kernel<0><<<dim3(INTER/128, TTOK/128), 256>>>(xf, sw1, g1, nullptr, TTOK, INTER, DIM);
    gemm_tf32_kernel<0><<<dim3(INTER/128, TTOK/128), 256>>>(xf, sw3, g3, nullptr, TTOK, INTER, DIM);
    silu_mul_kernel<<<(TTOK*INTER + 255)/256, 256>>>(g1, g3, hs, TTOK*INTER);
    gemm_tf32_kernel<0><<<dim3(DIM/128, TTOK/128), 256>>>(hs, sw2, z, nullptr, TTOK, DIM, INTER);
    // 12) final combine
    final_kernel<<<TTOK, 256>>>(out);
}

// round 3
// speedup vs baseline: 3.7180x; 1.7933x over previous
#include <cuda_runtime.h>
#include <cuda_bf16.h>
#include <math.h>
#include <stdint.h>

// ---------------- problem constants ----------------
#define TTOK   2048
#define BATCH  2
#define SEQ    1024
#define DIM    1024
#define HEADS  8
#define BH     16               // BATCH*HEADS
#define QK_HD  128
#define V_HD   128
#define NOPE   64
#define ROPE   64
#define KV_LORA 256
#define KVA_N  320
#define KVB_N  1536
#define N_EXP  32
#define N_GROUPS 8
#define TOPK   4
#define TOPK_G 4
#define INTER  512
#define NSLOT  8192
#define EPS    1e-6f
#define ATTN_SCALE 0.08838834764831843f

typedef __nv_bfloat16 bf16;

// ---------------- scratch ----------------
__device__ float g_kvF [TTOK * KVA_N];
__device__ float g_x2  [TTOK * DIM];
__device__ float g_xf  [TTOK * DIM];
__device__ float g_u1  [NSLOT * INTER];
__device__ float g_u3  [NSLOT * INTER];
__device__ float g_ybuf[NSLOT * DIM];
__device__ float g_g1  [TTOK * INTER];
__device__ float g_g3  [TTOK * INTER];
__device__ float g_zb  [TTOK * DIM];
__device__ float g_P   [(size_t)BH * SEQ * SEQ];   // 64MB scores

__device__ bf16 g_x1b [TTOK * DIM];
__device__ bf16 g_qb  [TTOK * DIM];
__device__ bf16 g_cnb [TTOK * KV_LORA];
__device__ bf16 g_kvpb[TTOK * KVB_N];
__device__ bf16 g_khb [(size_t)BH * SEQ * QK_HD];
__device__ bf16 g_Pb  [(size_t)BH * SEQ * SEQ];
__device__ bf16 g_attnb[TTOK * DIM];
__device__ bf16 g_xfb [TTOK * DIM];
__device__ bf16 g_hbufb[NSLOT * INTER];
__device__ bf16 g_hsb [TTOK * INTER];

__device__ int   g_counts [N_EXP];
__device__ int   g_offsets[N_EXP];
__device__ int   g_cursor [N_EXP];
__device__ int   g_expt_idx[NSLOT];
__device__ float g_expt_w [NSLOT];
__device__ int   g_perm_token[NSLOT];
__device__ float g_perm_w   [NSLOT];
__device__ int   g_slot_of  [NSLOT];

// ---------------- helpers ----------------
__device__ __forceinline__ float blockReduceSum256(float v) {
    __shared__ float red[8];
    int lane = threadIdx.x & 31, warp = threadIdx.x >> 5;
    #pragma unroll
    for (int o = 16; o > 0; o >>= 1) v += __shfl_xor_sync(0xffffffffu, v, o);
    if (lane == 0) red[warp] = v;
    __syncthreads();
    if (warp == 0) {
        v = (lane < 8) ? red[lane] : 0.f;
        #pragma unroll
        for (int o = 4; o > 0; o >>= 1) v += __shfl_xor_sync(0xffffffffu, v, o);
        if (lane == 0) red[0] = v;
    }
    __syncthreads();
    return red[0];
}

__device__ __forceinline__ float blockReduceMax256(float v) {
    __shared__ float red[8];
    int lane = threadIdx.x & 31, warp = threadIdx.x >> 5;
    #pragma unroll
    for (int o = 16; o > 0; o >>= 1) v = fmaxf(v, __shfl_xor_sync(0xffffffffu, v, o));
    if (lane == 0) red[warp] = v;
    __syncthreads();
    if (warp == 0) {
        v = (lane < 8) ? red[lane] : -1e30f;
        #pragma unroll
        for (int o = 4; o > 0; o >>= 1) v = fmaxf(v, __shfl_xor_sync(0xffffffffu, v, o));
        if (lane == 0) red[0] = v;
    }
    __syncthreads();
    return red[0];
}

__device__ __forceinline__ void mma_bf16(float* c, const uint32_t* a, const uint32_t* b) {
    asm volatile(
        "mma.sync.aligned.m16n8k16.row.col.f32.bf16.bf16.f32 "
        "{%0,%1,%2,%3}, {%4,%5,%6,%7}, {%8,%9}, {%0,%1,%2,%3};\n"
        : "+f"(c[0]), "+f"(c[1]), "+f"(c[2]), "+f"(c[3])
        : "r"(a[0]), "r"(a[1]), "r"(a[2]), "r"(a[3]), "r"(b[0]), "r"(b[1]));
}

// smem: 128 rows x 32 bf16 (64B rows = 16 4B-slots). sigma = k>>1.
__device__ __forceinline__ int swA(int row) { return ((row >> 1) & 3) << 2; }
__device__ __forceinline__ int swB(int col) { return (((col >> 1) & 3) << 2) ^ ((col >> 2) & 3); }

// ---------------- rmsnorm (optional fp32 + bf16 outputs) ----------------
__global__ void rmsnorm_kernel(const float* __restrict__ x, const float* __restrict__ w,
                               float* __restrict__ o32, bf16* __restrict__ o16,
                               int D, int in_stride) {
    int t = blockIdx.x;
    const float* row = x + (size_t)t * in_stride;
    float ss = 0.f;
    for (int d = threadIdx.x; d < D; d += 256) { float v = row[d]; ss += v * v; }
    ss = blockReduceSum256(ss);
    __shared__ float inv;
    if (threadIdx.x == 0) inv = rsqrtf(ss / (float)D + EPS);
    __syncthreads();
    for (int d = threadIdx.x; d < D; d += 256) {
        float v = row[d] * inv * w[d];
        if (o32) o32[(size_t)t * D + d] = v;
        if (o16) o16[(size_t)t * D + d] = __float2bfloat16_rn(v);
    }
}

// ---------------- bf16 tensor-core GEMM -----------------------------------
// MODE 0: dense (optional z-batched via strides); MODE 1: A rows gathered via
// g_perm_token per expert z; MODE 2: A rows = offset, C scaled by g_perm_w.
// BLAY: 0 = B fp32 [K][N]; 1 = B bf16 [K][N]; 2 = B bf16 [N][K] (row-major NK).
// CBF: C bf16 (else fp32, optional fp32 resid in MODE 0).
template<int MODE, int BLAY, bool CBF>
__global__ void __launch_bounds__(256)
gemm_k(const bf16* __restrict__ A, const void* __restrict__ Bv, void* __restrict__ Cv,
       const float* __restrict__ resid,
       int M, int N, int K, int lda, int ldb, int ldc, int zdiv,
       long long sA1, long long sA2, long long sB1, long long sB2,
       long long sC1, long long sC2) {
    __shared__ uint32_t As32[2][2048];
    __shared__ uint32_t Bs32[2][2048];

    int tid = threadIdx.x;
    int warp = tid >> 5, lane = tid & 31;
    int g = lane >> 2, tg = lane & 3;
    int wm = warp >> 2, wn = warp & 3;
    int m0w = wm * 64, n0w = wn * 32;

    int bn = blockIdx.x * 128;
    int bm = blockIdx.y * 128;
    int z = blockIdx.z;
    long long offA = (long long)(z / zdiv) * sA1 + (long long)(z % zdiv) * sA2;
    long long offB = (long long)(z / zdiv) * sB1 + (long long)(z % zdiv) * sB2;
    long long offC = (long long)(z / zdiv) * sC1 + (long long)(z % zdiv) * sC2;

    int cnt = M, base = 0;
    if (MODE != 0) {
        cnt = g_counts[z];
        base = g_offsets[z];
        if (bm >= cnt) return;
    }

    const bf16* Ap = A + offA;
    const float* Bf = (BLAY == 0) ? ((const float*)Bv + offB) : nullptr;
    const bf16*  Bh = (BLAY != 0) ? ((const bf16*)Bv + offB) : nullptr;

    float cacc[4][4][4];
    #pragma unroll
    for (int a = 0; a < 4; a++)
        #pragma unroll
        for (int b = 0; b < 4; b++)
            #pragma unroll
            for (int c = 0; c < 4; c++) cacc[a][b][c] = 0.f;

    uint4 rA[2];
    float4 rBf[4];
    uint4 rBh[2];

    // ---- stage: global -> regs ----
    auto stage = [&](int kk) {
        #pragma unroll
        for (int i = 0; i < 2; i++) {
            int fidx = tid + i * 256;
            int r = fidx >> 2, c8 = fidx & 3;
            uint4 v = make_uint4(0, 0, 0, 0);
            if (MODE == 0) {
                int row = bm + r;
                if (row < M) v = *(const uint4*)(Ap + (size_t)row * lda + kk + c8 * 8);
            } else if (MODE == 1) {
                if (bm + r < cnt) {
                    int tok = g_perm_token[base + bm + r];
                    v = *(const uint4*)(Ap + (size_t)tok * lda + kk + c8 * 8);
                }
            } else {
                if (bm + r < cnt)
                    v = *(const uint4*)(Ap + (size_t)(base + bm + r) * lda + kk + c8 * 8);
            }
            rA[i] = v;
        }
        if (BLAY == 0) {
            #pragma unroll
            for (int i = 0; i < 4; i++) {
                int fidx = tid + i * 256;
                int r = fidx >> 5, c4 = fidx & 31;
                int col = bn + c4 * 4;
                float4 v = make_float4(0.f, 0.f, 0.f, 0.f);
                if (col < N) v = *(const float4*)(Bf + (size_t)(kk + r) * ldb + col);
                rBf[i] = v;
            }
        } else if (BLAY == 1) {
            #pragma unroll
            for (int i = 0; i < 2; i++) {
                int fidx = tid + i * 256;
                int r = fidx >> 4, c8 = fidx & 15;
                int col = bn + c8 * 8;
                uint4 v = make_uint4(0, 0, 0, 0);
                if (col < N) v = *(const uint4*)(Bh + (size_t)(kk + r) * ldb + col);
                rBh[i] = v;
            }
        } else {
            #pragma unroll
            for (int i = 0; i < 2; i++) {
                int fidx = tid + i * 256;
                int r = fidx >> 2, c8 = fidx & 3;
                uint4 v = make_uint4(0, 0, 0, 0);
                if (bn + r < N) v = *(const uint4*)(Bh + (size_t)(bn + r) * ldb + kk + c8 * 8);
                rBh[i] = v;
            }
        }
    };

    // ---- commit: regs -> smem (swizzled) ----
    auto commit = [&](int buf) {
        #pragma unroll
        for (int i = 0; i < 2; i++) {
            int fidx = tid + i * 256;
            int r = fidx >> 2, c8 = fidx & 3;
            int slotblk = (c8 * 4) ^ swA(r);
            *(uint4*)&As32[buf][r * 16 + slotblk] = rA[i];
        }
        if (BLAY == 0) {
            uint16_t* Bs16 = (uint16_t*)Bs32[buf];
            #pragma unroll
            for (int i = 0; i < 4; i++) {
                int fidx = tid + i * 256;
                int r = fidx >> 5, c4 = fidx & 31;
                int sig = r >> 1, odd = r & 1;
                float vv[4] = {rBf[i].x, rBf[i].y, rBf[i].z, rBf[i].w};
                #pragma unroll
                for (int j = 0; j < 4; j++) {
                    int col = c4 * 4 + j;
                    bf16 hv = __float2bfloat16_rn(vv[j]);
                    Bs16[col * 32 + (sig ^ swB(col)) * 2 + odd] = *(uint16_t*)&hv;
                }
            }
        } else if (BLAY == 1) {
            uint16_t* Bs16 = (uint16_t*)Bs32[buf];
            #pragma unroll
            for (int i = 0; i < 2; i++) {
                int fidx = tid + i * 256;
                int r = fidx >> 4, c8 = fidx & 15;
                int sig = r >> 1, odd = r & 1;
                const uint16_t* src = (const uint16_t*)&rBh[i];
                #pragma unroll
                for (int j = 0; j < 8; j++) {
                    int col = c8 * 8 + j;
                    Bs16[col * 32 + (sig ^ swB(col)) * 2 + odd] = src[j];
                }
            }
        } else {
            #pragma unroll
            for (int i = 0; i < 2; i++) {
                int fidx = tid + i * 256;
                int r = fidx >> 2, c8 = fidx & 3;
                int slotblk = (c8 * 4) ^ swA(r);
                *(uint4*)&Bs32[buf][r * 16 + slotblk] = rBh[i];
            }
        }
    };

    auto compute = [&](int buf) {
        #pragma unroll
        for (int ks = 0; ks < 2; ks++) {
            int sb = ks * 8;
            uint32_t afr[4][4], bfr[4][2];
            #pragma unroll
            for (int mt = 0; mt < 4; mt++) {
                int r0 = m0w + mt * 16 + g;
                int r1 = r0 + 8;
                afr[mt][0] = As32[buf][r0 * 16 + ((sb + tg) ^ swA(r0))];
                afr[mt][1] = As32[buf][r1 * 16 + ((sb + tg) ^ swA(r1))];
                afr[mt][2] = As32[buf][r0 * 16 + ((sb + tg + 4) ^ swA(r0))];
                afr[mt][3] = As32[buf][r1 * 16 + ((sb + tg + 4) ^ swA(r1))];
            }
            #pragma unroll
            for (int nt = 0; nt < 4; nt++) {
                int c0 = n0w + nt * 8 + g;
                int sw = (BLAY == 2) ? swA(c0) : swB(c0);
                bfr[nt][0] = Bs32[buf][c0 * 16 + ((sb + tg) ^ sw)];
                bfr[nt][1] = Bs32[buf][c0 * 16 + ((sb + tg + 4) ^ sw)];
            }
            #pragma unroll
            for (int mt = 0; mt < 4; mt++)
                #pragma unroll
                for (int nt = 0; nt < 4; nt++)
                    mma_bf16(cacc[mt][nt], afr[mt], bfr[nt]);
        }
    };

    // ---- pipelined main loop (1 sync per K-tile) ----
    stage(0);
    commit(0);
    if (K > 32) stage(32);
    __syncthreads();
    int buf = 0;
    for (int kk = 0; kk < K; kk += 32) {
        if (kk + 32 < K) {
            commit(buf ^ 1);
            if (kk + 64 < K) stage(kk + 64);
        }
        compute(buf);
        __syncthreads();
        buf ^= 1;
    }

    // ---- epilogue ----
    float* Cf = (float*)Cv + offC;
    bf16* Ch = (bf16*)Cv + offC;
    #pragma unroll
    for (int mt = 0; mt < 4; mt++) {
        #pragma unroll
        for (int half = 0; half < 2; half++) {
            int lr = bm + m0w + mt * 16 + g + half * 8;
            bool rowok = (MODE == 0) ? (lr < M) : (lr < cnt);
            if (!rowok) continue;
            size_t orow = (MODE == 0) ? (size_t)lr : (size_t)(base + lr);
            float scale = (MODE == 2) ? g_perm_w[base + lr] : 1.f;
            #pragma unroll
            for (int nt = 0; nt < 4; nt++) {
                int col = bn + n0w + nt * 8 + 2 * tg;
                if (col >= N) continue;
                float v0 = cacc[mt][nt][half * 2 + 0];
                float v1 = cacc[mt][nt][half * 2 + 1];
                if (MODE == 2) { v0 *= scale; v1 *= scale; }
                if (CBF) {
                    __nv_bfloat162 bb = __floats2bfloat162_rn(v0, v1);
                    *(__nv_bfloat162*)(Ch + orow * ldc + col) = bb;
                } else {
                    if (MODE == 0 && resid) {
                        float2 rv = *(const float2*)(resid + orow * ldc + col);
                        v0 += rv.x; v1 += rv.y;
                    }
                    float2 ov = make_float2(v0, v1);
                    *(float2*)(Cf + orow * ldc + col) = ov;
                }
            }
        }
    }
}

// ---------------- pack per-head K (nope from kvp, rope from kv) -----------
__global__ void prep_k_kernel(const bf16* __restrict__ kvpb, const float* __restrict__ kvF,
                              bf16* __restrict__ kh) {
    long long i = (long long)blockIdx.x * 256 + threadIdx.x;
    if (i >= (long long)BH * SEQ * QK_HD) return;
    int d = (int)(i & 127);
    long long zs = i >> 7;
    int s = (int)(zs & (SEQ - 1));
    int zz = (int)(zs >> 10);
    int h = zz & 7, b = zz >> 3;
    size_t t = (size_t)b * SEQ + s;
    bf16 val;
    if (d < NOPE) val = kvpb[t * KVB_N + h * (NOPE + V_HD) + d];
    else          val = __float2bfloat16_rn(kvF[t * KVA_N + KV_LORA + (d - NOPE)]);
    kh[i] = val;
}

// ---------------- causal softmax (fp32 scores -> normalized bf16 P) -------
__global__ void softmax_kernel(const float* __restrict__ P, bf16* __restrict__ Pb) {
    int r = blockIdx.x;
    long long zoff = (long long)blockIdx.y * SEQ * SEQ + (long long)r * SEQ;
    const float* row = P + zoff;
    bf16* orow = Pb + zoff;
    int n = r + 1;
    int tid = threadIdx.x;
    float v[4];
    float m = -1e30f;
    #pragma unroll
    for (int j = 0; j < 4; j++) {
        int c = tid + j * 256;
        v[j] = (c < n) ? row[c] : -1e30f;
        m = fmaxf(m, v[j]);
    }
    m = blockReduceMax256(m);
    float e[4], l = 0.f;
    #pragma unroll
    for (int j = 0; j < 4; j++) {
        int c = tid + j * 256;
        e[j] = (c < n) ? __expf(ATTN_SCALE * (v[j] - m)) : 0.f;
        l += e[j];
    }
    l = blockReduceSum256(l);
    float inv = 1.f / l;
    #pragma unroll
    for (int j = 0; j < 4; j++) {
        int c = tid + j * 256;
        orow[c] = __float2bfloat16_rn(e[j] * inv);
    }
}

// ---------------- gate / routing ----------------
__global__ void zero_counts_kernel() {
    if (threadIdx.x < N_EXP) g_counts[threadIdx.x] = 0;
}

__global__ void gate_kernel(const float* __restrict__ xf, const float* __restrict__ gw,
                            const float* __restrict__ gb) {
    int t = blockIdx.x;
    __shared__ float sscore[N_EXP];
    int tid = threadIdx.x, warp = tid >> 5, lane = tid & 31;
    for (int e = warp; e < N_EXP; e += 4) {
        float s = 0.f;
        for (int d = lane; d < DIM; d += 32) s += xf[(size_t)t * DIM + d] * gw[(size_t)e * DIM + d];
        #pragma unroll
        for (int o = 16; o > 0; o >>= 1) s += __shfl_xor_sync(0xffffffffu, s, o);
        if (lane == 0) sscore[e] = 1.f / (1.f + expf(-s));
    }
    __syncthreads();
    if (tid == 0) {
        float orig[N_EXP], s[N_EXP];
        for (int e = 0; e < N_EXP; e++) { orig[e] = sscore[e]; s[e] = orig[e] + gb[e]; }
        float gs[N_GROUPS];
        for (int gg = 0; gg < N_GROUPS; gg++) {
            float m1 = -1e30f, m2 = -1e30f;
            for (int k = 0; k < 4; k++) {
                float v = s[gg * 4 + k];
                if (v > m1) { m2 = m1; m1 = v; } else if (v > m2) m2 = v;
            }
            gs[gg] = m1 + m2;
        }
        bool gsel[N_GROUPS] = {};
        for (int r = 0; r < TOPK_G; r++) {
            int best = -1; float bv = -1e30f;
            for (int gg = 0; gg < N_GROUPS; gg++)
                if (!gsel[gg] && gs[gg] > bv) { bv = gs[gg]; best = gg; }
            gsel[best] = true;
        }
        for (int gg = 0; gg < N_GROUPS; gg++)
            if (!gsel[gg]) for (int k = 0; k < 4; k++) s[gg * 4 + k] = -1e30f;
        int idx[TOPK]; bool used[N_EXP] = {};
        for (int r = 0; r < TOPK; r++) {
            int best = -1; float bv = -2e30f;
            for (int e = 0; e < N_EXP; e++)
                if (!used[e] && s[e] > bv) { bv = s[e]; best = e; }
            used[best] = true; idx[r] = best;
        }
        float wsum = 0.f;
        for (int r = 0; r < TOPK; r++) wsum += orig[idx[r]];
        float inv = 1.f / (wsum + 1e-20f);
        for (int r = 0; r < TOPK; r++) {
            g_expt_idx[t * TOPK + r] = idx[r];
            g_expt_w[t * TOPK + r] = orig[idx[r]] * inv;
            atomicAdd(&g_counts[idx[r]], 1);
        }
    }
}

__global__ void offsets_kernel() {
    if (threadIdx.x == 0) {
        int acc = 0;
        for (int e = 0; e < N_EXP; e++) {
            g_offsets[e] = acc;
            g_cursor[e] = acc;
            acc += g_counts[e];
        }
    }
}

__global__ void scatter_kernel() {
    int i = blockIdx.x * blockDim.x + threadIdx.x;
    if (i < NSLOT) {
        int e = g_expt_idx[i];
        int pos = atomicAdd(&g_cursor[e], 1);
        g_perm_token[pos] = i >> 2;
        g_perm_w[pos] = g_expt_w[i];
        g_slot_of[i] = pos;
    }
}

// ---------------- silu(a)*b -> bf16 ----------------
__global__ void silu_mul_kernel(const float* __restrict__ a, const float* __restrict__ b,
                                bf16* __restrict__ out, int n) {
    int i = blockIdx.x * blockDim.x + threadIdx.x;
    if (i < n) {
        float av = a[i];
        out[i] = __float2bfloat16_rn((av / (1.f + __expf(-av))) * b[i]);
    }
}

// ---------------- final combine ----------------
__global__ void final_kernel(float* __restrict__ out) {
    int t = blockIdx.x;
    int s0 = g_slot_of[t * 4 + 0], s1 = g_slot_of[t * 4 + 1];
    int s2 = g_slot_of[t * 4 + 2], s3 = g_slot_of[t * 4 + 3];
    for (int d = threadIdx.x; d < DIM; d += 256) {
        float v = g_x2[(size_t)t * DIM + d] + g_zb[(size_t)t * DIM + d];
        v += g_ybuf[(size_t)s0 * DIM + d];
        v += g_ybuf[(size_t)s1 * DIM + d];
        v += g_ybuf[(size_t)s2 * DIM + d];
        v += g_ybuf[(size_t)s3 * DIM + d];
        out[(size_t)t * DIM + d] = v;
    }
}

// ---------------- launcher ----------------
extern "C" void kernel_launch(void* const* d_in, const int* in_sizes, int n_in,
                              void* d_out, int out_size) {
    const float* x       = (const float*)d_in[0];
    const float* norm_a  = (const float*)d_in[1];
    const float* wq      = (const float*)d_in[2];
    const float* wkv_a   = (const float*)d_in[3];
    const float* kvnw    = (const float*)d_in[4];
    const float* wkv_b   = (const float*)d_in[5];
    const float* wo      = (const float*)d_in[6];
    const float* norm_m  = (const float*)d_in[7];
    const float* gate_w  = (const float*)d_in[8];
    const float* gate_b  = (const float*)d_in[9];
    const float* ew1     = (const float*)d_in[10];
    const float* ew2     = (const float*)d_in[11];
    const float* ew3     = (const float*)d_in[12];
    const float* sw1     = (const float*)d_in[13];
    const float* sw2     = (const float*)d_in[14];
    const float* sw3     = (const float*)d_in[15];
    float* out = (float*)d_out;

    float *kvF, *x2, *xf, *u1, *u3, *ybuf, *g1, *g3, *zb, *P;
    bf16 *x1b, *qb, *cnb, *kvpb, *khb, *Pb, *attnb, *xfb, *hbufb, *hsb;
    cudaGetSymbolAddress((void**)&kvF, g_kvF);
    cudaGetSymbolAddress((void**)&x2,  g_x2);
    cudaGetSymbolAddress((void**)&xf,  g_xf);
    cudaGetSymbolAddress((void**)&u1,  g_u1);
    cudaGetSymbolAddress((void**)&u3,  g_u3);
    cudaGetSymbolAddress((void**)&ybuf,g_ybuf);
    cudaGetSymbolAddress((void**)&g1,  g_g1);
    cudaGetSymbolAddress((void**)&g3,  g_g3);
    cudaGetSymbolAddress((void**)&zb,  g_zb);
    cudaGetSymbolAddress((void**)&P,   g_P);
    cudaGetSymbolAddress((void**)&x1b, g_x1b);
    cudaGetSymbolAddress((void**)&qb,  g_qb);
    cudaGetSymbolAddress((void**)&cnb, g_cnb);
    cudaGetSymbolAddress((void**)&kvpb,g_kvpb);
    cudaGetSymbolAddress((void**)&khb, g_khb);
    cudaGetSymbolAddress((void**)&Pb,  g_Pb);
    cudaGetSymbolAddress((void**)&attnb, g_attnb);
    cudaGetSymbolAddress((void**)&xfb, g_xfb);
    cudaGetSymbolAddress((void**)&hbufb, g_hbufb);
    cudaGetSymbolAddress((void**)&hsb, g_hsb);

    // 1) attention input norm -> bf16
    rmsnorm_kernel<<<TTOK, 256>>>(x, norm_a, nullptr, x1b, DIM, DIM);
    // 2) q = x1 @ wq (bf16 out)
    gemm_k<0,0,true><<<dim3(8,16,1), 256>>>(x1b, wq, qb, nullptr,
        TTOK, DIM, DIM, DIM, DIM, DIM, 1, 0,0,0,0,0,0);
    // 3) kv = x1 @ wkv_a (fp32 out)
    gemm_k<0,0,false><<<dim3(3,16,1), 256>>>(x1b, wkv_a, kvF, nullptr,
        TTOK, KVA_N, DIM, DIM, KVA_N, KVA_N, 1, 0,0,0,0,0,0);
    // 4) cn = rmsnorm(kv[:, :256]) -> bf16
    rmsnorm_kernel<<<TTOK, 256>>>(kvF, kvnw, nullptr, cnb, KV_LORA, KVA_N);
    // 5) kvp = cn @ wkv_b (bf16 out)
    gemm_k<0,0,true><<<dim3(12,16,1), 256>>>(cnb, wkv_b, kvpb, nullptr,
        TTOK, KVB_N, KV_LORA, KV_LORA, KVB_N, KVB_N, 1, 0,0,0,0,0,0);
    // 6) pack per-head K
    prep_k_kernel<<<(int)(((long long)BH*SEQ*QK_HD + 255)/256), 256>>>(kvpb, kvF, khb);
    // 7) scores = q @ kh^T  (batched over z=16, B in NK layout)
    gemm_k<0,2,false><<<dim3(8,8,BH), 256>>>(qb, khb, P, nullptr,
        SEQ, SEQ, QK_HD, DIM, QK_HD, SEQ, HEADS,
        (long long)SEQ*DIM, 128,
        (long long)HEADS*SEQ*QK_HD, (long long)SEQ*QK_HD,
        (long long)HEADS*SEQ*SEQ, (long long)SEQ*SEQ);
    // 8) causal softmax -> normalized bf16 P
    softmax_kernel<<<dim3(SEQ, BH), 256>>>(P, Pb);
    // 9) attn = P @ V  (V read strided from kvpb)
    gemm_k<0,1,true><<<dim3(1,8,BH), 256>>>(Pb, kvpb + NOPE, attnb, nullptr,
        SEQ, V_HD, SEQ, SEQ, KVB_N, DIM, HEADS,
        (long long)HEADS*SEQ*SEQ, (long long)SEQ*SEQ,
        (long long)SEQ*KVB_N, (long long)(NOPE+V_HD),
        (long long)SEQ*DIM, 128);
    // 10) x2 = x + attn @ wo
    gemm_k<0,0,false><<<dim3(8,16,1), 256>>>(attnb, wo, x2, x,
        TTOK, DIM, DIM, DIM, DIM, DIM, 1, 0,0,0,0,0,0);
    // 11) moe input norm (fp32 for gate + bf16 for GEMMs)
    rmsnorm_kernel<<<TTOK, 256>>>(x2, norm_m, xf, xfb, DIM, DIM);
    // 12) gate + routing
    zero_counts_kernel<<<1, 32>>>();
    gate_kernel<<<TTOK, 128>>>(xf, gate_w, gate_b);
    offsets_kernel<<<1, 32>>>();
    scatter_kernel<<<NSLOT/256, 256>>>();
    // 13) routed experts
    gemm_k<1,0,false><<<dim3(4,16,N_EXP), 256>>>(xfb, ew1, u1, nullptr,
        0, INTER, DIM, DIM, INTER, INTER, 1, 0,0, (long long)DIM*INTER,0, 0,0);
    gemm_k<1,0,false><<<dim3(4,16,N_EXP), 256>>>(xfb, ew3, u3, nullptr,
        0, INTER, DIM, DIM, INTER, INTER, 1, 0,0, (long long)DIM*INTER,0, 0,0);
    silu_mul_kernel<<<(NSLOT*INTER)/256, 256>>>(u1, u3, hbufb, NSLOT*INTER);
    gemm_k<2,0,false><<<dim3(8,16,N_EXP), 256>>>(hbufb, ew2, ybuf, nullptr,
        0, DIM, INTER, INTER, DIM, DIM, 1, 0,0, (long long)INTER*DIM,0, 0,0);
    // 14) shared expert
    gemm_k<0,0,false><<<dim3(4,16,1), 256>>>(xfb, sw1, g1, nullptr,
        TTOK, INTER, DIM, DIM, INTER, INTER, 1, 0,0,0,0,0,0);
    gemm_k<0,0,false><<<dim3(4,16,1), 256>>>(xfb, sw3, g3, nullptr,
        TTOK, INTER, DIM, DIM, INTER, INTER, 1, 0,0,0,0,0,0);
    silu_mul_kernel<<<(TTOK*INTER)/256, 256>>>(g1, g3, hsb, TTOK*INTER);
    gemm_k<0,0,false><<<dim3(8,16,1), 256>>>(hsb, sw2, zb, nullptr,
        TTOK, DIM, INTER, INTER, DIM, DIM, 1, 0,0,0,0,0,0);
    // 15) final combine
    final_kernel<<<TTOK, 256>>>(out);
}

// round 4
// speedup vs baseline: 3.9321x; 1.0576x over previous
#include <cuda_runtime.h>
#include <cuda_fp16.h>
#include <math.h>
#include <stdint.h>

// ---------------- problem constants ----------------
#define TTOK   2048
#define BATCH  2
#define SEQ    1024
#define DIM    1024
#define HEADS  8
#define BH     16
#define QK_HD  128
#define V_HD   128
#define NOPE   64
#define ROPE   64
#define KV_LORA 256
#define KVA_N  320
#define KVB_N  1536
#define N_EXP  32
#define N_GROUPS 8
#define TOPK   4
#define TOPK_G 4
#define INTER  512
#define NSLOT  8192
#define EPS    1e-6f
#define ATTN_SCALE 0.08838834764831843f

typedef __half f16;

// ---------------- scratch ----------------
__device__ float g_kvF [TTOK * KVA_N];
__device__ float g_x2  [TTOK * DIM];
__device__ float g_xf  [TTOK * DIM];
__device__ float g_ybuf[NSLOT * DIM];
__device__ float g_zb  [TTOK * DIM];
__device__ float g_P   [(size_t)BH * SEQ * SEQ];

__device__ f16 g_x1h [TTOK * DIM];
__device__ f16 g_qh  [TTOK * DIM];
__device__ f16 g_cnh [TTOK * KV_LORA];
__device__ f16 g_kvph[TTOK * KVB_N];
__device__ f16 g_khh [(size_t)BH * SEQ * QK_HD];
__device__ f16 g_Ph  [(size_t)BH * SEQ * SEQ];
__device__ f16 g_attnh[TTOK * DIM];
__device__ f16 g_xfh [TTOK * DIM];
__device__ f16 g_hbufh[NSLOT * INTER];
__device__ f16 g_hsh [TTOK * INTER];

__device__ int   g_counts [N_EXP];
__device__ int   g_offsets[N_EXP];
__device__ int   g_cursor [N_EXP];
__device__ int   g_expt_idx[NSLOT];
__device__ float g_expt_w [NSLOT];
__device__ int   g_perm_token[NSLOT];
__device__ float g_perm_w   [NSLOT];
__device__ int   g_slot_of  [NSLOT];

// ---------------- helpers ----------------
__device__ __forceinline__ float blockReduceSum256(float v) {
    __shared__ float red[8];
    int lane = threadIdx.x & 31, warp = threadIdx.x >> 5;
    #pragma unroll
    for (int o = 16; o > 0; o >>= 1) v += __shfl_xor_sync(0xffffffffu, v, o);
    if (lane == 0) red[warp] = v;
    __syncthreads();
    if (warp == 0) {
        v = (lane < 8) ? red[lane] : 0.f;
        #pragma unroll
        for (int o = 4; o > 0; o >>= 1) v += __shfl_xor_sync(0xffffffffu, v, o);
        if (lane == 0) red[0] = v;
    }
    __syncthreads();
    return red[0];
}

__device__ __forceinline__ float blockReduceMax256(float v) {
    __shared__ float red[8];
    int lane = threadIdx.x & 31, warp = threadIdx.x >> 5;
    #pragma unroll
    for (int o = 16; o > 0; o >>= 1) v = fmaxf(v, __shfl_xor_sync(0xffffffffu, v, o));
    if (lane == 0) red[warp] = v;
    __syncthreads();
    if (warp == 0) {
        v = (lane < 8) ? red[lane] : -1e30f;
        #pragma unroll
        for (int o = 4; o > 0; o >>= 1) v = fmaxf(v, __shfl_xor_sync(0xffffffffu, v, o));
        if (lane == 0) red[0] = v;
    }
    __syncthreads();
    return red[0];
}

__device__ __forceinline__ void mma_f16(float* c, const uint32_t* a, const uint32_t* b) {
    asm volatile(
        "mma.sync.aligned.m16n8k16.row.col.f32.f16.f16.f32 "
        "{%0,%1,%2,%3}, {%4,%5,%6,%7}, {%8,%9}, {%0,%1,%2,%3};\n"
        : "+f"(c[0]), "+f"(c[1]), "+f"(c[2]), "+f"(c[3])
        : "r"(a[0]), "r"(a[1]), "r"(a[2]), "r"(a[3]), "r"(b[0]), "r"(b[1]));
}

__device__ __forceinline__ int swA(int row) { return ((row >> 1) & 3) << 2; }
__device__ __forceinline__ int swB(int col) { return (((col >> 1) & 3) << 2) ^ ((col >> 2) & 3); }

__device__ __forceinline__ float silu_f(float a) { return a / (1.f + __expf(-a)); }

// ---------------- rmsnorm ----------------
__global__ void rmsnorm_kernel(const float* __restrict__ x, const float* __restrict__ w,
                               float* __restrict__ o32, f16* __restrict__ o16,
                               int D, int in_stride) {
    int t = blockIdx.x;
    const float* row = x + (size_t)t * in_stride;
    float ss = 0.f;
    for (int d = threadIdx.x; d < D; d += 256) { float v = row[d]; ss += v * v; }
    ss = blockReduceSum256(ss);
    __shared__ float inv;
    if (threadIdx.x == 0) inv = rsqrtf(ss / (float)D + EPS);
    __syncthreads();
    for (int d = threadIdx.x; d < D; d += 256) {
        float v = row[d] * inv * w[d];
        if (o32) o32[(size_t)t * D + d] = v;
        if (o16) o16[(size_t)t * D + d] = __float2half_rn(v);
    }
}

// ---------------- fp16 tensor-core GEMM -----------------------------------
// MODE 0: dense; MODE 1: A rows gathered via g_perm_token (expert z);
// MODE 2: A rows at expert offset, C scaled by g_perm_w.
// BLAY: 0 = B fp32 [K][N]; 1 = B f16 [K][N]; 2 = B f16 [N][K].
// CBF: C f16 (else fp32 + optional resid).
// CAUSAL: 0 none; 1 = triangular tile decode from blockIdx.x; 2 = K clipped at bm+128.
template<int MODE, int BLAY, bool CBF, int CAUSAL>
__global__ void __launch_bounds__(256)
gemm_k(const f16* __restrict__ A, const void* __restrict__ Bv, void* __restrict__ Cv,
       const float* __restrict__ resid,
       int M, int N, int K, int lda, int ldb, int ldc, int zdiv,
       long long sA1, long long sA2, long long sB1, long long sB2,
       long long sC1, long long sC2) {
    __shared__ uint32_t As32[2][2048];
    __shared__ uint32_t Bs32[2][2048];
    __shared__ int stoks[128];

    int tid = threadIdx.x;
    int warp = tid >> 5, lane = tid & 31;
    int g = lane >> 2, tg = lane & 3;
    int wm = warp >> 2, wn = warp & 3;
    int m0w = wm * 64, n0w = wn * 32;

    int bn, bm;
    if (CAUSAL == 1) {
        int ti = blockIdx.x;
        int bmt = 0;
        while ((bmt + 1) * (bmt + 2) / 2 <= ti) bmt++;
        int bnt = ti - bmt * (bmt + 1) / 2;
        bm = bmt * 128; bn = bnt * 128;
    } else {
        bn = blockIdx.x * 128;
        bm = blockIdx.y * 128;
    }
    int z = blockIdx.z;
    long long offA = (long long)(z / zdiv) * sA1 + (long long)(z % zdiv) * sA2;
    long long offB = (long long)(z / zdiv) * sB1 + (long long)(z % zdiv) * sB2;
    long long offC = (long long)(z / zdiv) * sC1 + (long long)(z % zdiv) * sC2;

    int cnt = M, base = 0;
    if (MODE != 0) {
        cnt = g_counts[z];
        base = g_offsets[z];
        if (bm >= cnt) return;
    }
    if (MODE == 1) {
        if (tid < 128) stoks[tid] = (bm + tid < cnt) ? g_perm_token[base + bm + tid] : 0;
        __syncthreads();
    }

    const f16* Ap = A + offA;
    const float* Bf = (BLAY == 0) ? ((const float*)Bv + offB) : nullptr;
    const f16*  Bh = (BLAY != 0) ? ((const f16*)Bv + offB) : nullptr;

    int Keff = K;
    if (CAUSAL == 2) { int kl = bm + 128; Keff = kl < K ? kl : K; }

    float cacc[4][4][4];
    #pragma unroll
    for (int a = 0; a < 4; a++)
        #pragma unroll
        for (int b = 0; b < 4; b++)
            #pragma unroll
            for (int c = 0; c < 4; c++) cacc[a][b][c] = 0.f;

    uint4 rA[2];
    float4 rBf[4];
    uint4 rBh[2];

    auto stage = [&](int kk) {
        #pragma unroll
        for (int i = 0; i < 2; i++) {
            int fidx = tid + i * 256;
            int r = fidx >> 2, c8 = fidx & 3;
            uint4 v = make_uint4(0, 0, 0, 0);
            if (MODE == 0) {
                int row = bm + r;
                if (row < M) v = *(const uint4*)(Ap + (size_t)row * lda + kk + c8 * 8);
            } else if (MODE == 1) {
                if (bm + r < cnt) {
                    int tok = stoks[r];
                    v = *(const uint4*)(Ap + (size_t)tok * lda + kk + c8 * 8);
                }
            } else {
                if (bm + r < cnt)
                    v = *(const uint4*)(Ap + (size_t)(base + bm + r) * lda + kk + c8 * 8);
            }
            rA[i] = v;
        }
        if (BLAY == 0) {
            #pragma unroll
            for (int i = 0; i < 4; i++) {
                int fidx = tid + i * 256;
                int r = fidx >> 5, c4 = fidx & 31;
                int col = bn + c4 * 4;
                float4 v = make_float4(0.f, 0.f, 0.f, 0.f);
                if (col < N) v = *(const float4*)(Bf + (size_t)(kk + r) * ldb + col);
                rBf[i] = v;
            }
        } else if (BLAY == 1) {
            #pragma unroll
            for (int i = 0; i < 2; i++) {
                int fidx = tid + i * 256;
                int r = fidx >> 4, c8 = fidx & 15;
                int col = bn + c8 * 8;
                uint4 v = make_uint4(0, 0, 0, 0);
                if (col < N) v = *(const uint4*)(Bh + (size_t)(kk + r) * ldb + col);
                rBh[i] = v;
            }
        } else {
            #pragma unroll
            for (int i = 0; i < 2; i++) {
                int fidx = tid + i * 256;
                int r = fidx >> 2, c8 = fidx & 3;
                uint4 v = make_uint4(0, 0, 0, 0);
                if (bn + r < N) v = *(const uint4*)(Bh + (size_t)(bn + r) * ldb + kk + c8 * 8);
                rBh[i] = v;
            }
        }
    };

    auto commit = [&](int buf) {
        #pragma unroll
        for (int i = 0; i < 2; i++) {
            int fidx = tid + i * 256;
            int r = fidx >> 2, c8 = fidx & 3;
            int slotblk = (c8 * 4) ^ swA(r);
            *(uint4*)&As32[buf][r * 16 + slotblk] = rA[i];
        }
        if (BLAY == 0) {
            uint16_t* Bs16 = (uint16_t*)Bs32[buf];
            #pragma unroll
            for (int i = 0; i < 4; i++) {
                int fidx = tid + i * 256;
                int r = fidx >> 5, c4 = fidx & 31;
                int sig = r >> 1, odd = r & 1;
                float vv[4] = {rBf[i].x, rBf[i].y, rBf[i].z, rBf[i].w};
                #pragma unroll
                for (int j = 0; j < 4; j++) {
                    int col = c4 * 4 + j;
                    f16 hv = __float2half_rn(vv[j]);
                    Bs16[col * 32 + (sig ^ swB(col)) * 2 + odd] = *(uint16_t*)&hv;
                }
            }
        } else if (BLAY == 1) {
            uint16_t* Bs16 = (uint16_t*)Bs32[buf];
            #pragma unroll
            for (int i = 0; i < 2; i++) {
                int fidx = tid + i * 256;
                int r = fidx >> 4, c8 = fidx & 15;
                int sig = r >> 1, odd = r & 1;
                const uint16_t* src = (const uint16_t*)&rBh[i];
                #pragma unroll
                for (int j = 0; j < 8; j++) {
                    int col = c8 * 8 + j;
                    Bs16[col * 32 + (sig ^ swB(col)) * 2 + odd] = src[j];
                }
            }
        } else {
            #pragma unroll
            for (int i = 0; i < 2; i++) {
                int fidx = tid + i * 256;
                int r = fidx >> 2, c8 = fidx & 3;
                int slotblk = (c8 * 4) ^ swA(r);
                *(uint4*)&Bs32[buf][r * 16 + slotblk] = rBh[i];
            }
        }
    };

    auto compute = [&](int buf) {
        #pragma unroll
        for (int ks = 0; ks < 2; ks++) {
            int sb = ks * 8;
            uint32_t afr[4][4], bfr[4][2];
            #pragma unroll
            for (int mt = 0; mt < 4; mt++) {
                int r0 = m0w + mt * 16 + g;
                int r1 = r0 + 8;
                afr[mt][0] = As32[buf][r0 * 16 + ((sb + tg) ^ swA(r0))];
                afr[mt][1] = As32[buf][r1 * 16 + ((sb + tg) ^ swA(r1))];
                afr[mt][2] = As32[buf][r0 * 16 + ((sb + tg + 4) ^ swA(r0))];
                afr[mt][3] = As32[buf][r1 * 16 + ((sb + tg + 4) ^ swA(r1))];
            }
            #pragma unroll
            for (int nt = 0; nt < 4; nt++) {
                int c0 = n0w + nt * 8 + g;
                int sw = (BLAY == 2) ? swA(c0) : swB(c0);
                bfr[nt][0] = Bs32[buf][c0 * 16 + ((sb + tg) ^ sw)];
                bfr[nt][1] = Bs32[buf][c0 * 16 + ((sb + tg + 4) ^ sw)];
            }
            #pragma unroll
            for (int mt = 0; mt < 4; mt++)
                #pragma unroll
                for (int nt = 0; nt < 4; nt++)
                    mma_f16(cacc[mt][nt], afr[mt], bfr[nt]);
        }
    };

    stage(0);
    commit(0);
    if (Keff > 32) stage(32);
    __syncthreads();
    int buf = 0;
    for (int kk = 0; kk < Keff; kk += 32) {
        if (kk + 32 < Keff) {
            commit(buf ^ 1);
            if (kk + 64 < Keff) stage(kk + 64);
        }
        compute(buf);
        __syncthreads();
        buf ^= 1;
    }

    float* Cf = (float*)Cv + offC;
    f16* Ch = (f16*)Cv + offC;
    #pragma unroll
    for (int mt = 0; mt < 4; mt++) {
        #pragma unroll
        for (int half_ = 0; half_ < 2; half_++) {
            int lr = bm + m0w + mt * 16 + g + half_ * 8;
            bool rowok = (MODE == 0) ? (lr < M) : (lr < cnt);
            if (!rowok) continue;
            size_t orow = (MODE == 0) ? (size_t)lr : (size_t)(base + lr);
            float scale = (MODE == 2) ? g_perm_w[base + lr] : 1.f;
            #pragma unroll
            for (int nt = 0; nt < 4; nt++) {
                int col = bn + n0w + nt * 8 + 2 * tg;
                if (col >= N) continue;
                float v0 = cacc[mt][nt][half_ * 2 + 0];
                float v1 = cacc[mt][nt][half_ * 2 + 1];
                if (MODE == 2) { v0 *= scale; v1 *= scale; }
                if (CBF) {
                    *(__half2*)(Ch + orow * ldc + col) = __floats2half2_rn(v0, v1);
                } else {
                    if (MODE == 0 && resid) {
                        float2 rv = *(const float2*)(resid + orow * ldc + col);
                        v0 += rv.x; v1 += rv.y;
                    }
                    *(float2*)(Cf + orow * ldc + col) = make_float2(v0, v1);
                }
            }
        }
    }
}

// ---------------- fused gated up-proj: C = silu(A@B1) * (A@B3), f16 out ----
// MODE 0: dense rows; MODE 1: rows gathered via g_perm_token (expert z).
template<int MODE>
__global__ void __launch_bounds__(256)
gemm_dual(const f16* __restrict__ A, const float* __restrict__ B1g,
          const float* __restrict__ B3g, f16* __restrict__ C,
          int M, int N, int K, int lda, long long sB) {
    __shared__ uint32_t As32[2][2048];
    __shared__ uint32_t B1s32[2][2048];
    __shared__ uint32_t B3s32[2][2048];
    __shared__ int stoks[128];

    int tid = threadIdx.x;
    int warp = tid >> 5, lane = tid & 31;
    int g = lane >> 2, tg = lane & 3;
    int wm = warp >> 2, wn = warp & 3;
    int m0w = wm * 64, n0w = wn * 32;

    int bn = blockIdx.x * 128;
    int bm = blockIdx.y * 128;
    int z = blockIdx.z;

    int cnt = M, base = 0;
    if (MODE == 1) {
        cnt = g_counts[z];
        base = g_offsets[z];
        if (bm >= cnt) return;
        if (tid < 128) stoks[tid] = (bm + tid < cnt) ? g_perm_token[base + bm + tid] : 0;
        __syncthreads();
    }
    const float* B1 = B1g + (long long)z * sB;
    const float* B3 = B3g + (long long)z * sB;

    float acc1[4][4][4], acc3[4][4][4];
    #pragma unroll
    for (int a = 0; a < 4; a++)
        #pragma unroll
        for (int b = 0; b < 4; b++)
            #pragma unroll
            for (int c = 0; c < 4; c++) { acc1[a][b][c] = 0.f; acc3[a][b][c] = 0.f; }

    uint4 rA[2];
    float4 rB1[4], rB3[4];

    auto stage = [&](int kk) {
        #pragma unroll
        for (int i = 0; i < 2; i++) {
            int fidx = tid + i * 256;
            int r = fidx >> 2, c8 = fidx & 3;
            uint4 v = make_uint4(0, 0, 0, 0);
            if (MODE == 0) {
                if (bm + r < M) v = *(const uint4*)(A + (size_t)(bm + r) * lda + kk + c8 * 8);
            } else {
                if (bm + r < cnt) {
                    int tok = stoks[r];
                    v = *(const uint4*)(A + (size_t)tok * lda + kk + c8 * 8);
                }
            }
            rA[i] = v;
        }
        #pragma unroll
        for (int i = 0; i < 4; i++) {
            int fidx = tid + i * 256;
            int r = fidx >> 5, c4 = fidx & 31;
            int col = bn + c4 * 4;
            float4 v1 = make_float4(0.f, 0.f, 0.f, 0.f);
            float4 v3 = v1;
            if (col < N) {
                v1 = *(const float4*)(B1 + (size_t)(kk + r) * N + col);
                v3 = *(const float4*)(B3 + (size_t)(kk + r) * N + col);
            }
            rB1[i] = v1; rB3[i] = v3;
        }
    };

    auto commit = [&](int buf) {
        #pragma unroll
        for (int i = 0; i < 2; i++) {
            int fidx = tid + i * 256;
            int r = fidx >> 2, c8 = fidx & 3;
            int slotblk = (c8 * 4) ^ swA(r);
            *(uint4*)&As32[buf][r * 16 + slotblk] = rA[i];
        }
        uint16_t* b1 = (uint16_t*)B1s32[buf];
        uint16_t* b3 = (uint16_t*)B3s32[buf];
        #pragma unroll
        for (int i = 0; i < 4; i++) {
            int fidx = tid + i * 256;
            int r = fidx >> 5, c4 = fidx & 31;
            int sig = r >> 1, odd = r & 1;
            float w1[4] = {rB1[i].x, rB1[i].y, rB1[i].z, rB1[i].w};
            float w3[4] = {rB3[i].x, rB3[i].y, rB3[i].z, rB3[i].w};
            #pragma unroll
            for (int j = 0; j < 4; j++) {
                int col = c4 * 4 + j;
                int slot = (sig ^ swB(col)) * 2 + odd;
                f16 h1 = __float2half_rn(w1[j]);
                f16 h3 = __float2half_rn(w3[j]);
                b1[col * 32 + slot] = *(uint16_t*)&h1;
                b3[col * 32 + slot] = *(uint16_t*)&h3;
            }
        }
    };

    auto compute = [&](int buf) {
        #pragma unroll
        for (int ks = 0; ks < 2; ks++) {
            int sb = ks * 8;
            uint32_t afr[4][4], b1fr[4][2], b3fr[4][2];
            #pragma unroll
            for (int mt = 0; mt < 4; mt++) {
                int r0 = m0w + mt * 16 + g;
                int r1 = r0 + 8;
                afr[mt][0] = As32[buf][r0 * 16 + ((sb + tg) ^ swA(r0))];
                afr[mt][1] = As32[buf][r1 * 16 + ((sb + tg) ^ swA(r1))];
                afr[mt][2] = As32[buf][r0 * 16 + ((sb + tg + 4) ^ swA(r0))];
                afr[mt][3] = As32[buf][r1 * 16 + ((sb + tg + 4) ^ swA(r1))];
            }
            #pragma unroll
            for (int nt = 0; nt < 4; nt++) {
                int c0 = n0w + nt * 8 + g;
                int sw = swB(c0);
                b1fr[nt][0] = B1s32[buf][c0 * 16 + ((sb + tg) ^ sw)];
                b1fr[nt][1] = B1s32[buf][c0 * 16 + ((sb + tg + 4) ^ sw)];
                b3fr[nt][0] = B3s32[buf][c0 * 16 + ((sb + tg) ^ sw)];
                b3fr[nt][1] = B3s32[buf][c0 * 16 + ((sb + tg + 4) ^ sw)];
            }
            #pragma unroll
            for (int mt = 0; mt < 4; mt++)
                #pragma unroll
                for (int nt = 0; nt < 4; nt++) {
                    mma_f16(acc1[mt][nt], afr[mt], b1fr[nt]);
                    mma_f16(acc3[mt][nt], afr[mt], b3fr[nt]);
                }
        }
    };

    stage(0);
    commit(0);
    if (K > 32) stage(32);
    __syncthreads();
    int buf = 0;
    for (int kk = 0; kk < K; kk += 32) {
        if (kk + 32 < K) {
            commit(buf ^ 1);
            if (kk + 64 < K) stage(kk + 64);
        }
        compute(buf);
        __syncthreads();
        buf ^= 1;
    }

    #pragma unroll
    for (int mt = 0; mt < 4; mt++) {
        #pragma unroll
        for (int half_ = 0; half_ < 2; half_++) {
            int lr = bm + m0w + mt * 16 + g + half_ * 8;
            bool rowok = (MODE == 0) ? (lr < M) : (lr < cnt);
            if (!rowok) continue;
            size_t orow = (MODE == 0) ? (size_t)lr : (size_t)(base + lr);
            #pragma unroll
            for (int nt = 0; nt < 4; nt++) {
                int col = bn + n0w + nt * 8 + 2 * tg;
                if (col >= N) continue;
                float a0 = acc1[mt][nt][half_ * 2 + 0];
                float a1 = acc1[mt][nt][half_ * 2 + 1];
                float b0 = acc3[mt][nt][half_ * 2 + 0];
                float b1 = acc3[mt][nt][half_ * 2 + 1];
                *(__half2*)(C + orow * N + col) =
                    __floats2half2_rn(silu_f(a0) * b0, silu_f(a1) * b1);
            }
        }
    }
}

// ---------------- pack per-head K ----------------
__global__ void prep_k_kernel(const f16* __restrict__ kvph, const float* __restrict__ kvF,
                              f16* __restrict__ kh) {
    long long i = (long long)blockIdx.x * 256 + threadIdx.x;
    if (i >= (long long)BH * SEQ * QK_HD) return;
    int d = (int)(i & 127);
    long long zs = i >> 7;
    int s = (int)(zs & (SEQ - 1));
    int zz = (int)(zs >> 10);
    int h = zz & 7, b = zz >> 3;
    size_t t = (size_t)b * SEQ + s;
    f16 val;
    if (d < NOPE) val = kvph[t * KVB_N + h * (NOPE + V_HD) + d];
    else          val = __float2half_rn(kvF[t * KVA_N + KV_LORA + (d - NOPE)]);
    kh[i] = val;
}

// ---------------- causal softmax ----------------
__global__ void softmax_kernel(const float* __restrict__ P, f16* __restrict__ Ph) {
    int r = blockIdx.x;
    long long zoff = (long long)blockIdx.y * SEQ * SEQ + (long long)r * SEQ;
    const float* row = P + zoff;
    f16* orow = Ph + zoff;
    int n = r + 1;
    int tid = threadIdx.x;
    float v[4];
    float m = -1e30f;
    #pragma unroll
    for (int j = 0; j < 4; j++) {
        int c = tid + j * 256;
        v[j] = (c < n) ? row[c] : -1e30f;
        m = fmaxf(m, v[j]);
    }
    m = blockReduceMax256(m);
    float e[4], l = 0.f;
    #pragma unroll
    for (int j = 0; j < 4; j++) {
        int c = tid + j * 256;
        e[j] = (c < n) ? __expf(ATTN_SCALE * (v[j] - m)) : 0.f;
        l += e[j];
    }
    l = blockReduceSum256(l);
    float inv = 1.f / l;
    #pragma unroll
    for (int j = 0; j < 4; j++) {
        int c = tid + j * 256;
        orow[c] = __float2half_rn(e[j] * inv);
    }
}

// ---------------- gate / routing ----------------
__global__ void zero_counts_kernel() {
    if (threadIdx.x < N_EXP) g_counts[threadIdx.x] = 0;
}

__global__ void gate_kernel(const float* __restrict__ xf, const float* __restrict__ gw,
                            const float* __restrict__ gb) {
    int t = blockIdx.x;
    __shared__ float sscore[N_EXP];
    int tid = threadIdx.x, warp = tid >> 5, lane = tid & 31;
    for (int e = warp; e < N_EXP; e += 4) {
        float s = 0.f;
        for (int d = lane; d < DIM; d += 32) s += xf[(size_t)t * DIM + d] * gw[(size_t)e * DIM + d];
        #pragma unroll
        for (int o = 16; o > 0; o >>= 1) s += __shfl_xor_sync(0xffffffffu, s, o);
        if (lane == 0) sscore[e] = 1.f / (1.f + expf(-s));
    }
    __syncthreads();
    if (tid == 0) {
        float orig[N_EXP], s[N_EXP];
        for (int e = 0; e < N_EXP; e++) { orig[e] = sscore[e]; s[e] = orig[e] + gb[e]; }
        float gs[N_GROUPS];
        for (int gg = 0; gg < N_GROUPS; gg++) {
            float m1 = -1e30f, m2 = -1e30f;
            for (int k = 0; k < 4; k++) {
                float v = s[gg * 4 + k];
                if (v > m1) { m2 = m1; m1 = v; } else if (v > m2) m2 = v;
            }
            gs[gg] = m1 + m2;
        }
        bool gsel[N_GROUPS] = {};
        for (int r = 0; r < TOPK_G; r++) {
            int best = -1; float bv = -1e30f;
            for (int gg = 0; gg < N_GROUPS; gg++)
                if (!gsel[gg] && gs[gg] > bv) { bv = gs[gg]; best = gg; }
            gsel[best] = true;
        }
        for (int gg = 0; gg < N_GROUPS; gg++)
            if (!gsel[gg]) for (int k = 0; k < 4; k++) s[gg * 4 + k] = -1e30f;
        int idx[TOPK]; bool used[N_EXP] = {};
        for (int r = 0; r < TOPK; r++) {
            int best = -1; float bv = -2e30f;
            for (int e = 0; e < N_EXP; e++)
                if (!used[e] && s[e] > bv) { bv = s[e]; best = e; }
            used[best] = true; idx[r] = best;
        }
        float wsum = 0.f;
        for (int r = 0; r < TOPK; r++) wsum += orig[idx[r]];
        float inv = 1.f / (wsum + 1e-20f);
        for (int r = 0; r < TOPK; r++) {
            g_expt_idx[t * TOPK + r] = idx[r];
            g_expt_w[t * TOPK + r] = orig[idx[r]] * inv;
            atomicAdd(&g_counts[idx[r]], 1);
        }
    }
}

__global__ void offsets_kernel() {
    if (threadIdx.x == 0) {
        int acc = 0;
        for (int e = 0; e < N_EXP; e++) {
            g_offsets[e] = acc;
            g_cursor[e] = acc;
            acc += g_counts[e];
        }
    }
}

__global__ void scatter_kernel() {
    int i = blockIdx.x * blockDim.x + threadIdx.x;
    if (i < NSLOT) {
        int e = g_expt_idx[i];
        int pos = atomicAdd(&g_cursor[e], 1);
        g_perm_token[pos] = i >> 2;
        g_perm_w[pos] = g_expt_w[i];
        g_slot_of[i] = pos;
    }
}

// ---------------- final combine ----------------
__global__ void final_kernel(float* __restrict__ out) {
    int t = blockIdx.x;
    int s0 = g_slot_of[t * 4 + 0], s1 = g_slot_of[t * 4 + 1];
    int s2 = g_slot_of[t * 4 + 2], s3 = g_slot_of[t * 4 + 3];
    for (int d = threadIdx.x; d < DIM; d += 256) {
        float v = g_x2[(size_t)t * DIM + d] + g_zb[(size_t)t * DIM + d];
        v += g_ybuf[(size_t)s0 * DIM + d];
        v += g_ybuf[(size_t)s1 * DIM + d];
        v += g_ybuf[(size_t)s2 * DIM + d];
        v += g_ybuf[(size_t)s3 * DIM + d];
        out[(size_t)t * DIM + d] = v;
    }
}

// ---------------- launcher ----------------
extern "C" void kernel_launch(void* const* d_in, const int* in_sizes, int n_in,
                              void* d_out, int out_size) {
    const float* x       = (const float*)d_in[0];
    const float* norm_a  = (const float*)d_in[1];
    const float* wq      = (const float*)d_in[2];
    const float* wkv_a   = (const float*)d_in[3];
    const float* kvnw    = (const float*)d_in[4];
    const float* wkv_b   = (const float*)d_in[5];
    const float* wo      = (const float*)d_in[6];
    const float* norm_m  = (const float*)d_in[7];
    const float* gate_w  = (const float*)d_in[8];
    const float* gate_b  = (const float*)d_in[9];
    const float* ew1     = (const float*)d_in[10];
    const float* ew2     = (const float*)d_in[11];
    const float* ew3     = (const float*)d_in[12];
    const float* sw1     = (const float*)d_in[13];
    const float* sw2     = (const float*)d_in[14];
    const float* sw3     = (const float*)d_in[15];
    float* out = (float*)d_out;

    float *kvF, *x2, *xf, *ybuf, *zb, *P;
    f16 *x1h, *qh, *cnh, *kvph, *khh, *Ph, *attnh, *xfh, *hbufh, *hsh;
    cudaGetSymbolAddress((void**)&kvF, g_kvF);
    cudaGetSymbolAddress((void**)&x2,  g_x2);
    cudaGetSymbolAddress((void**)&xf,  g_xf);
    cudaGetSymbolAddress((void**)&ybuf,g_ybuf);
    cudaGetSymbolAddress((void**)&zb,  g_zb);
    cudaGetSymbolAddress((void**)&P,   g_P);
    cudaGetSymbolAddress((void**)&x1h, g_x1h);
    cudaGetSymbolAddress((void**)&qh,  g_qh);
    cudaGetSymbolAddress((void**)&cnh, g_cnh);
    cudaGetSymbolAddress((void**)&kvph,g_kvph);
    cudaGetSymbolAddress((void**)&khh, g_khh);
    cudaGetSymbolAddress((void**)&Ph,  g_Ph);
    cudaGetSymbolAddress((void**)&attnh, g_attnh);
    cudaGetSymbolAddress((void**)&xfh, g_xfh);
    cudaGetSymbolAddress((void**)&hbufh, g_hbufh);
    cudaGetSymbolAddress((void**)&hsh, g_hsh);

    // 1) attention input norm -> fp16
    rmsnorm_kernel<<<TTOK, 256>>>(x, norm_a, nullptr, x1h, DIM, DIM);
    // 2) q = x1 @ wq
    gemm_k<0,0,true,0><<<dim3(8,16,1), 256>>>(x1h, wq, qh, nullptr,
        TTOK, DIM, DIM, DIM, DIM, DIM, 1, 0,0,0,0,0,0);
    // 3) kv = x1 @ wkv_a
    gemm_k<0,0,false,0><<<dim3(3,16,1), 256>>>(x1h, wkv_a, kvF, nullptr,
        TTOK, KVA_N, DIM, DIM, KVA_N, KVA_N, 1, 0,0,0,0,0,0);
    // 4) cn = rmsnorm(kv[:, :256])
    rmsnorm_kernel<<<TTOK, 256>>>(kvF, kvnw, nullptr, cnh, KV_LORA, KVA_N);
    // 5) kvp = cn @ wkv_b
    gemm_k<0,0,true,0><<<dim3(12,16,1), 256>>>(cnh, wkv_b, kvph, nullptr,
        TTOK, KVB_N, KV_LORA, KV_LORA, KVB_N, KVB_N, 1, 0,0,0,0,0,0);
    // 6) pack per-head K
    prep_k_kernel<<<(int)(((long long)BH*SEQ*QK_HD + 255)/256), 256>>>(kvph, kvF, khh);
    // 7) scores = q @ kh^T, lower-triangular tiles only
    gemm_k<0,2,false,1><<<dim3(36,1,BH), 256>>>(qh, khh, P, nullptr,
        SEQ, SEQ, QK_HD, DIM, QK_HD, SEQ, HEADS,
        (long long)SEQ*DIM, 128,
        (long long)HEADS*SEQ*QK_HD, (long long)SEQ*QK_HD,
        (long long)HEADS*SEQ*SEQ, (long long)SEQ*SEQ);
    // 8) causal softmax -> normalized fp16 P
    softmax_kernel<<<dim3(SEQ, BH), 256>>>(P, Ph);
    // 9) attn = P @ V with causal K-limit
    gemm_k<0,1,true,2><<<dim3(1,8,BH), 256>>>(Ph, kvph + NOPE, attnh, nullptr,
        SEQ, V_HD, SEQ, SEQ, KVB_N, DIM, HEADS,
        (long long)HEADS*SEQ*SEQ, (long long)SEQ*SEQ,
        (long long)SEQ*KVB_N, (long long)(NOPE+V_HD),
        (long long)SEQ*DIM, 128);
    // 10) x2 = x + attn @ wo
    gemm_k<0,0,false,0><<<dim3(8,16,1), 256>>>(attnh, wo, x2, x,
        TTOK, DIM, DIM, DIM, DIM, DIM, 1, 0,0,0,0,0,0);
    // 11) moe input norm
    rmsnorm_kernel<<<TTOK, 256>>>(x2, norm_m, xf, xfh, DIM, DIM);
    // 12) gate + routing
    zero_counts_kernel<<<1, 32>>>();
    gate_kernel<<<TTOK, 128>>>(xf, gate_w, gate_b);
    offsets_kernel<<<1, 32>>>();
    scatter_kernel<<<NSLOT/256, 256>>>();
    // 13) routed experts: fused gated up-proj, then weighted down-proj
    gemm_dual<1><<<dim3(4,16,N_EXP), 256>>>(xfh, ew1, ew3, hbufh,
        0, INTER, DIM, DIM, (long long)DIM*INTER);
    gemm_k<2,0,false,0><<<dim3(8,16,N_EXP), 256>>>(hbufh, ew2, ybuf, nullptr,
        0, DIM, INTER, INTER, DIM, DIM, 1, 0,0, (long long)INTER*DIM,0, 0,0);
    // 14) shared expert: fused gated up-proj, then down-proj
    gemm_dual<0><<<dim3(4,16,1), 256>>>(xfh, sw1, sw3, hsh,
        TTOK, INTER, DIM, DIM, 0);
    gemm_k<0,0,false,0><<<dim3(8,16,1), 256>>>(hsh, sw2, zb, nullptr,
        TTOK, DIM, INTER, INTER, DIM, DIM, 1, 0,0,0,0,0,0);
    // 15) final combine
    final_kernel<<<TTOK, 256>>>(out);
}